// round 8
// baseline (speedup 1.0000x reference)
#include <cuda_runtime.h>
#include <cuda_fp16.h>
#include <math.h>
#include <cstdint>

#define BB 4
#define CC 256
#define TT 16
#define HH 32
#define WW 32
#define KCB 1024
#define GG 16
#define HWp (HH*WW)          // 1024
#define THW (TT*HWp)         // 16384
#define NN (BB*THW)          // 65536
#define EPSV 1e-6f

#define SXV 64.0f
#define SWV 64.0f
#define SEV 16384.0f
#define ALPHA_CONV (1.0f/(64.0f*64.0f))
#define ALPHA_DIST (-2.0f/(64.0f*16384.0f))
#define REFINE_TH 2e-4f

// ---- output layout ----
#define SZ_ZQ     (BB*CC*THW)
#define OFF_LOSS  (SZ_ZQ)
#define OFF_LOSS2 (SZ_ZQ+1)
#define OFF_INDS  (SZ_ZQ+2)
#define OFF_INDT  (OFF_INDS+NN)
#define OFF_PERPS (OFF_INDT+NN)
#define OFF_PERPT (OFF_PERPS+1)

// ---- scratch ----
__device__ float g_zp[NN*CC];
__device__ float g_q [NN*CC];
__device__ float g_k [NN*CC];
__device__ float g_v [NN*CC];
__device__ __half g_dist[NN*KCB];    // s = embsq[c] - 2 x.e  (row-constant removed)
__device__ __half g_p1h[NN*CC];
__device__ __half g_p1l[NN*CC];
__device__ __half g_p2h[NN*CC];
__device__ __half g_wh[4*CC*CC];
__device__ __half g_wl[4*CC*CC];
__device__ __half g_ebh[2*KCB*CC];
__device__ float g_xsq[2*NN];
__device__ float g_embsq[2*KCB];
__device__ float g_mu[BB*GG];
__device__ float g_rstd[BB*GG];
__device__ double g_sumd[2*BB*GG];
__device__ int   g_idx[2*NN];
__device__ float g_avg[2*KCB];
__device__ int   g_hist[2*KCB];
__device__ double g_mse;

// ================= helpers =================
__device__ __forceinline__ uint32_t smem_u32(const void* p) {
    uint32_t a;
    asm("{ .reg .u64 t; cvta.to.shared.u64 t, %1; cvt.u32.u64 %0, t; }" : "=r"(a) : "l"(p));
    return a;
}
__device__ __forceinline__ float rcp_approx(float x) {
    float r;
    asm("rcp.approx.ftz.f32 %0, %1;" : "=f"(r) : "f"(x));
    return r;
}
#define CP_ASYNC16(dst, src) \
    asm volatile("cp.async.cg.shared.global [%0], [%1], 16;" :: "r"(dst), "l"(src))
#define CP_COMMIT() asm volatile("cp.async.commit_group;" ::: "memory")
#define CP_WAIT1()  asm volatile("cp.async.wait_group 1;" ::: "memory")

__device__ __forceinline__ void ldsm_x4(uint32_t* r, uint32_t addr) {
    asm volatile("ldmatrix.sync.aligned.m8n8.x4.shared.b16 {%0,%1,%2,%3}, [%4];"
        : "=r"(r[0]), "=r"(r[1]), "=r"(r[2]), "=r"(r[3]) : "r"(addr));
}
__device__ __forceinline__ void mma16816(float* d, const uint32_t* a, const uint32_t* b) {
    asm volatile("mma.sync.aligned.m16n8k16.row.col.f32.f16.f16.f32 "
        "{%0,%1,%2,%3}, {%4,%5,%6,%7}, {%8,%9}, {%0,%1,%2,%3};"
        : "+f"(d[0]), "+f"(d[1]), "+f"(d[2]), "+f"(d[3])
        : "r"(a[0]), "r"(a[1]), "r"(a[2]), "r"(a[3]), "r"(b[0]), "r"(b[1]));
}
__device__ __forceinline__ void split16(float v, __half* hp, __half* lp) {
    __half h = __float2half_rn(v);
    *hp = h;
    *lp = __float2half_rn(v - __half2float(h));
}

// ================= small kernels =================

__global__ void zero_kernel() {
    int i = blockIdx.x*256 + threadIdx.x;   // grid 512 -> 131072 threads
    if (i < 2*KCB) { g_avg[i] = 0.f; g_hist[i] = 0; }
    if (i < 2*BB*GG) g_sumd[i] = 0.0;
    if (i == 0) g_mse = 0.0;
    g_xsq[i] = 0.f;                          // i < 2*NN always
}

__global__ void embsplit_kernel(const float* __restrict__ es, const float* __restrict__ et) {
    int row = blockIdx.x, c = threadIdx.x;
    const float* src = (row < KCB) ? (es + (size_t)row*CC) : (et + (size_t)(row-KCB)*CC);
    float v = src[c];
    g_ebh[(size_t)row*CC + c] = __float2half_rn(v*SEV);
    float s = v*v;
    #pragma unroll
    for (int off = 16; off; off >>= 1) s += __shfl_xor_sync(0xffffffffu, s, off);
    __shared__ float red[8];
    if ((c & 31) == 0) red[c >> 5] = s;
    __syncthreads();
    if (c == 0) {
        float t = 0.f;
        #pragma unroll
        for (int j = 0; j < 8; j++) t += red[j];
        g_embsq[row] = t;
    }
}

__global__ void wsplit_kernel(const float* __restrict__ wq, const float* __restrict__ wk,
                              const float* __restrict__ wv, const float* __restrict__ wp) {
    int i = blockIdx.x*256 + threadIdx.x;
    int seg = i >> 16, j = i & 65535;
    const float* src = seg == 0 ? wq : seg == 1 ? wk : seg == 2 ? wv : wp;
    split16(src[j]*SWV, &g_wh[i], &g_wl[i]);
}

__global__ void __launch_bounds__(256) gn_partial(const float* __restrict__ z) {
    int blk = blockIdx.x;
    int bg = blk >> 5, chunk = blk & 31;
    const float4* p = (const float4*)(z + (size_t)bg*(16*THW) + (size_t)chunk*8192);
    float s = 0.f, s2 = 0.f;
    #pragma unroll
    for (int i = 0; i < 8; i++) {
        float4 v = p[threadIdx.x + i*256];
        s  += v.x + v.y + v.z + v.w;
        s2 += v.x*v.x + v.y*v.y + v.z*v.z + v.w*v.w;
    }
    __shared__ float ss[256], ss2[256];
    ss[threadIdx.x] = s; ss2[threadIdx.x] = s2;
    __syncthreads();
    for (int k = 128; k; k >>= 1) {
        if (threadIdx.x < k) { ss[threadIdx.x] += ss[threadIdx.x+k]; ss2[threadIdx.x] += ss2[threadIdx.x+k]; }
        __syncthreads();
    }
    if (threadIdx.x == 0) {
        atomicAdd(&g_sumd[bg], (double)ss[0]);
        atomicAdd(&g_sumd[64 + bg], (double)ss2[0]);
    }
}

__global__ void gn_final() {
    int bg = threadIdx.x;
    double cnt = (double)(16*THW);
    double mu = g_sumd[bg]/cnt;
    double var = g_sumd[64+bg]/cnt - mu*mu;
    g_mu[bg] = (float)mu;
    g_rstd[bg] = rsqrtf((float)var + EPSV);
}

// transpose + groupnorm + fused xsq[branch 0]
__global__ void transpose_norm_kernel(const float* __restrict__ z,
                                      const float* __restrict__ gamma,
                                      const float* __restrict__ beta) {
    __shared__ float tl[32][33];
    int b = blockIdx.z, c0 = blockIdx.y*32, s0 = blockIdx.x*32;
    int tx = threadIdx.x, ty = threadIdx.y;
    #pragma unroll
    for (int i = 0; i < 4; i++) {
        int c = c0 + ty + i*8;
        tl[ty + i*8][tx] = z[((size_t)(b*CC + c))*THW + s0 + tx];
    }
    __syncthreads();
    #pragma unroll
    for (int i = 0; i < 4; i++) {
        int th = s0 + ty + i*8;
        int c  = c0 + tx;
        float v = tl[tx][ty + i*8];
        size_t o = ((size_t)(b*THW + th))*CC + c;
        g_zp[o] = v;
        g_p2h[o] = __float2half_rn(v*SXV);
        int bg = b*GG + (c >> 4);
        float hn = (v - g_mu[bg]) * g_rstd[bg] * gamma[c] + beta[c];
        split16(hn*SXV, &g_p1h[o], &g_p1l[o]);
        float sq = v*v;
        #pragma unroll
        for (int off = 16; off; off >>= 1) sq += __shfl_xor_sync(0xffffffffu, sq, off);
        if (tx == 0) atomicAdd(&g_xsq[b*THW + th], sq);
    }
}

// ================= HMMA GEMMs =================
#define PITCH 80
#define TILE_B (128*PITCH)
#define STAGE3_B (4*TILE_B)
#define GSM3 (2*STAGE3_B)     // 81920
#define STAGE1_B (2*TILE_B)
#define GSM1 (2*STAGE1_B)     // 40960

__device__ __forceinline__ void g_load_stage3(
        uint32_t sb, int stage, int kc,
        const __half* Ah, const __half* Al,
        const __half* Bh, const __half* Bl,
        int row0, int col0, int tid) {
    int k0 = kc*32;
    uint32_t sbase = sb + stage*STAGE3_B;
    #pragma unroll
    for (int j = 0; j < 8; j++) {
        int idx = j*256 + tid;
        int t = idx >> 9;
        int r = (idx >> 2) & 127;
        int s = idx & 3;
        const __half* gsrc;
        if (t < 2) gsrc = (t ? Al : Ah) + (size_t)(row0 + r)*CC + k0 + s*8;
        else       gsrc = (t == 2 ? Bh : Bl) + (size_t)(col0 + r)*CC + k0 + s*8;
        uint32_t dst = sbase + t*TILE_B + r*PITCH + s*16;
        CP_ASYNC16(dst, gsrc);
    }
}

// conv GEMM (3-pass fp16 split). fuse!=0: proj path -> ztf = out + diff(zp),
// writes fp32 Out, p1h (scaled fp16 hi), and xsq partials.
__global__ void __launch_bounds__(256)
gemm3fp16(const __half* __restrict__ Ah, const __half* __restrict__ Al,
          const __half* __restrict__ Bh, const __half* __restrict__ Bl,
          const float* __restrict__ colv,
          const float* __restrict__ zp, float* __restrict__ xsqout,
          __half* __restrict__ p1hout, int fuse,
          float* __restrict__ Out, int out_ld, float alpha) {
    extern __shared__ char smem[];
    uint32_t sb = smem_u32(smem);
    int tid = threadIdx.x, wid = tid >> 5, lane = tid & 31;
    int row0 = blockIdx.y * 128, col0 = blockIdx.x * 128;
    int m_base = (wid & 3) * 32;
    int n_base = (wid >> 2) * 64;

    float acc[2][8][4];
    #pragma unroll
    for (int mt = 0; mt < 2; mt++)
        #pragma unroll
        for (int nt = 0; nt < 8; nt++)
            #pragma unroll
            for (int i = 0; i < 4; i++) acc[mt][nt][i] = 0.f;

    uint32_t a_roff = (uint32_t)(m_base + (lane & 15)) * PITCH + ((lane >> 4) * 16);
    uint32_t b_roff = (uint32_t)(n_base + ((lane >> 4) * 8) + (lane & 7)) * PITCH + (((lane >> 3) & 1) * 16);

    g_load_stage3(sb, 0, 0, Ah, Al, Bh, Bl, row0, col0, tid);
    CP_COMMIT();

    for (int kc = 0; kc < 8; kc++) {
        if (kc + 1 < 8) g_load_stage3(sb, (kc+1) & 1, kc+1, Ah, Al, Bh, Bl, row0, col0, tid);
        CP_COMMIT();
        CP_WAIT1();
        __syncthreads();
        uint32_t st = sb + (kc & 1)*STAGE3_B;
        #pragma unroll
        for (int ks = 0; ks < 2; ks++) {
            uint32_t koff = ks * 32;
            uint32_t ah[2][4], al[2][4], bh[8][2], bl[8][2];
            #pragma unroll
            for (int mt = 0; mt < 2; mt++) {
                uint32_t ad = st + a_roff + (uint32_t)mt*16*PITCH + koff;
                ldsm_x4(ah[mt], ad);
                ldsm_x4(al[mt], ad + TILE_B);
            }
            #pragma unroll
            for (int p = 0; p < 4; p++) {
                uint32_t r4[4];
                uint32_t bd = st + 2*TILE_B + b_roff + (uint32_t)p*16*PITCH + koff;
                ldsm_x4(r4, bd);
                bh[2*p][0] = r4[0]; bh[2*p][1] = r4[1];
                bh[2*p+1][0] = r4[2]; bh[2*p+1][1] = r4[3];
                ldsm_x4(r4, bd + TILE_B);
                bl[2*p][0] = r4[0]; bl[2*p][1] = r4[1];
                bl[2*p+1][0] = r4[2]; bl[2*p+1][1] = r4[3];
            }
            #pragma unroll
            for (int mt = 0; mt < 2; mt++)
                #pragma unroll
                for (int nt = 0; nt < 8; nt++) {
                    mma16816(acc[mt][nt], ah[mt], bh[nt]);
                    mma16816(acc[mt][nt], ah[mt], bl[nt]);
                    mma16816(acc[mt][nt], al[mt], bh[nt]);
                }
        }
        __syncthreads();
    }

    int g = lane >> 2, t4 = lane & 3;
    if (!fuse) {
        #pragma unroll
        for (int mt = 0; mt < 2; mt++) {
            int r_lo = row0 + m_base + mt*16 + g;
            int r_hi = r_lo + 8;
            #pragma unroll
            for (int nt = 0; nt < 8; nt++) {
                int c = col0 + n_base + nt*8 + 2*t4;
                float cv0 = colv[c], cv1 = colv[c+1];
                *(float2*)(Out + (size_t)r_lo*out_ld + c) =
                    make_float2(fmaf(alpha, acc[mt][nt][0], cv0), fmaf(alpha, acc[mt][nt][1], cv1));
                *(float2*)(Out + (size_t)r_hi*out_ld + c) =
                    make_float2(fmaf(alpha, acc[mt][nt][2], cv0), fmaf(alpha, acc[mt][nt][3], cv1));
            }
        }
    } else {
        #pragma unroll
        for (int mt = 0; mt < 2; mt++) {
            #pragma unroll
            for (int half_i = 0; half_i < 2; half_i++) {
                int r = row0 + m_base + mt*16 + g + half_i*8;
                int t = (r >> 10) & 15;      // (r / HWp) % TT
                float sq = 0.f;
                #pragma unroll
                for (int nt = 0; nt < 8; nt++) {
                    int c = col0 + n_base + nt*8 + 2*t4;
                    size_t idx = (size_t)r*out_ld + c;
                    float2 zc = *(const float2*)(zp + idx);
                    float2 zm = t ? *(const float2*)(zp + idx - (size_t)HWp*CC) : zc;
                    float a0 = half_i ? acc[mt][nt][2] : acc[mt][nt][0];
                    float a1 = half_i ? acc[mt][nt][3] : acc[mt][nt][1];
                    float v0 = fmaf(alpha, a0, colv[c])   + (zc.x - zm.x);
                    float v1 = fmaf(alpha, a1, colv[c+1]) + (zc.y - zm.y);
                    *(float2*)(Out + idx) = make_float2(v0, v1);
                    *(__half2*)(p1hout + idx) = __floats2half2_rn(v0*SXV, v1*SXV);
                    sq += v0*v0 + v1*v1;
                }
                sq += __shfl_xor_sync(0xffffffffu, sq, 1);
                sq += __shfl_xor_sync(0xffffffffu, sq, 2);
                if (t4 == 0) atomicAdd(&xsqout[r], sq);
            }
        }
    }
}

// single-pass dist GEMM; stores s = embsq[c] - 2 x.e as fp16 (row-constant dropped)
__device__ __forceinline__ void g_load_stage1(
        uint32_t sb, int stage, int kc,
        const __half* Ah, const __half* Bh,
        int row0, int col0, int tid) {
    int k0 = kc*32;
    uint32_t sbase = sb + stage*STAGE1_B;
    #pragma unroll
    for (int j = 0; j < 4; j++) {
        int idx = j*256 + tid;
        int t = idx >> 9;
        int r = (idx >> 2) & 127;
        int s = idx & 3;
        const __half* gsrc = (t ? Bh + (size_t)(col0 + r)*CC : Ah + (size_t)(row0 + r)*CC) + k0 + s*8;
        uint32_t dst = sbase + t*TILE_B + r*PITCH + s*16;
        CP_ASYNC16(dst, gsrc);
    }
}

__global__ void __launch_bounds__(256)
gemm_dist(const __half* __restrict__ Ah, const __half* __restrict__ Bh,
          const float* __restrict__ colv,
          __half* __restrict__ OutH, int out_ld, float alpha) {
    extern __shared__ char smem[];
    uint32_t sb = smem_u32(smem);
    int tid = threadIdx.x, wid = tid >> 5, lane = tid & 31;
    int row0 = blockIdx.y * 128, col0 = blockIdx.x * 128;
    int m_base = (wid & 3) * 32;
    int n_base = (wid >> 2) * 64;

    float acc[2][8][4];
    #pragma unroll
    for (int mt = 0; mt < 2; mt++)
        #pragma unroll
        for (int nt = 0; nt < 8; nt++)
            #pragma unroll
            for (int i = 0; i < 4; i++) acc[mt][nt][i] = 0.f;

    uint32_t a_roff = (uint32_t)(m_base + (lane & 15)) * PITCH + ((lane >> 4) * 16);
    uint32_t b_roff = (uint32_t)(n_base + ((lane >> 4) * 8) + (lane & 7)) * PITCH + (((lane >> 3) & 1) * 16);

    g_load_stage1(sb, 0, 0, Ah, Bh, row0, col0, tid);
    CP_COMMIT();

    for (int kc = 0; kc < 8; kc++) {
        if (kc + 1 < 8) g_load_stage1(sb, (kc+1) & 1, kc+1, Ah, Bh, row0, col0, tid);
        CP_COMMIT();
        CP_WAIT1();
        __syncthreads();
        uint32_t st = sb + (kc & 1)*STAGE1_B;
        #pragma unroll
        for (int ks = 0; ks < 2; ks++) {
            uint32_t koff = ks * 32;
            uint32_t ah[2][4], bh[8][2];
            #pragma unroll
            for (int mt = 0; mt < 2; mt++)
                ldsm_x4(ah[mt], st + a_roff + (uint32_t)mt*16*PITCH + koff);
            #pragma unroll
            for (int p = 0; p < 4; p++) {
                uint32_t r4[4];
                ldsm_x4(r4, st + TILE_B + b_roff + (uint32_t)p*16*PITCH + koff);
                bh[2*p][0] = r4[0]; bh[2*p][1] = r4[1];
                bh[2*p+1][0] = r4[2]; bh[2*p+1][1] = r4[3];
            }
            #pragma unroll
            for (int mt = 0; mt < 2; mt++)
                #pragma unroll
                for (int nt = 0; nt < 8; nt++)
                    mma16816(acc[mt][nt], ah[mt], bh[nt]);
        }
        __syncthreads();
    }

    int g = lane >> 2, t4 = lane & 3;
    #pragma unroll
    for (int mt = 0; mt < 2; mt++) {
        int r_lo = row0 + m_base + mt*16 + g;
        int r_hi = r_lo + 8;
        #pragma unroll
        for (int nt = 0; nt < 8; nt++) {
            int c = col0 + n_base + nt*8 + 2*t4;
            float cv0 = colv[c], cv1 = colv[c+1];
            *(__half2*)(OutH + (size_t)r_lo*out_ld + c) =
                __floats2half2_rn(fmaf(alpha, acc[mt][nt][0], cv0), fmaf(alpha, acc[mt][nt][1], cv1));
            *(__half2*)(OutH + (size_t)r_hi*out_ld + c) =
                __floats2half2_rn(fmaf(alpha, acc[mt][nt][2], cv0), fmaf(alpha, acc[mt][nt][3], cv1));
        }
    }
}

// ================= attention =================
#define APAD 260
__global__ void __launch_bounds__(256) attn_kernel() {
    __shared__ float qs[16][APAD], ks[16][APAD];
    __shared__ float att[16][16];
    int x = blockIdx.x;
    int b = x >> 10;
    int s = x & (HWp - 1);
    size_t base = ((size_t)(b*TT)*HWp + s)*CC;
    const size_t tstr = (size_t)HWp*CC;
    int tid = threadIdx.x;
    for (int e = tid; e < 16*256; e += 256) {
        int t = e >> 8, c = e & 255;
        qs[t][c] = g_q[base + (size_t)t*tstr + c];
        ks[t][c] = g_k[base + (size_t)t*tstr + c];
    }
    __syncthreads();
    int i = tid >> 4, j = tid & 15;
    float acc = 0.f;
    #pragma unroll 8
    for (int c4 = 0; c4 < 64; c4++) {
        float4 a = *(const float4*)&qs[i][c4*4];
        float4 bb = *(const float4*)&ks[j][c4*4];
        acc = fmaf(a.x, bb.x, acc); acc = fmaf(a.y, bb.y, acc);
        acc = fmaf(a.z, bb.z, acc); acc = fmaf(a.w, bb.w, acc);
    }
    att[i][j] = acc * 0.0625f;
    __syncthreads();
    if (tid < 16) {
        float m = -3.4e38f;
        for (int jj = 0; jj < 16; jj++) m = fmaxf(m, att[tid][jj]);
        float ssum = 0.f;
        for (int jj = 0; jj < 16; jj++) { float e = expf(att[tid][jj]-m); att[tid][jj] = e; ssum += e; }
        float r = 1.0f/ssum;
        for (int jj = 0; jj < 16; jj++) att[tid][jj] *= r;
    }
    __syncthreads();
    int c = tid;
    float vv[16];
    #pragma unroll
    for (int tk = 0; tk < 16; tk++) vv[tk] = g_v[base + (size_t)tk*tstr + c];
    #pragma unroll
    for (int tq = 0; tq < 16; tq++) {
        float o = 0.f;
        #pragma unroll
        for (int tk = 0; tk < 16; tk++) o += att[tq][tk]*vv[tk];
        size_t oi = base + (size_t)tq*tstr + c;
        split16(o*SXV, &g_p1h[oi], &g_p1l[oi]);
    }
}

// warp-per-row reduce: d = xsq[row] + s(fp16); iv = rcp(d); argmax iv + refine; avg
__global__ void __launch_bounds__(256) vq_reduce_kernel(int branch, const float* __restrict__ X,
                                                        const float* __restrict__ EMB) {
    __shared__ float swarp[8][1024];
    int tid = threadIdx.x, w = tid >> 5, lane = tid & 31;
    int row0 = blockIdx.x * 64;
    float accx[16], accy[16];
    #pragma unroll
    for (int j = 0; j < 16; j++) { accx[j] = 0.f; accy[j] = 0.f; }
    for (int rr = 0; rr < 8; rr++) {
        int row = row0 + w*8 + rr;
        const __half2* dr = (const __half2*)(g_dist + (size_t)row*KCB);
        float sA = g_xsq[branch*NN + row];
        float ivx[16], ivy[16];
        float lsum = 0.f, m1v = 0.f, m2v = 0.f; int i1 = 0;
        #pragma unroll
        for (int j = 0; j < 16; j++) {
            float2 s2 = __half22float2(dr[j*32 + lane]);
            float ix = rcp_approx(sA + s2.x);
            float iy = rcp_approx(sA + s2.y);
            ivx[j] = ix; ivy[j] = iy; lsum += ix + iy;
            int cb = 2*(j*32 + lane);
            if (ix > m1v) { m2v = m1v; m1v = ix; i1 = cb; } else m2v = fmaxf(m2v, ix);
            if (iy > m1v) { m2v = m1v; m1v = iy; i1 = cb+1; } else m2v = fmaxf(m2v, iy);
        }
        #pragma unroll
        for (int o = 16; o; o >>= 1) {
            lsum += __shfl_xor_sync(0xffffffffu, lsum, o);
            float o1 = __shfl_xor_sync(0xffffffffu, m1v, o);
            int   oi = __shfl_xor_sync(0xffffffffu, i1, o);
            float o2 = __shfl_xor_sync(0xffffffffu, m2v, o);
            if (o1 > m1v || (o1 == m1v && oi < i1)) { m2v = fmaxf(m1v, o2); m1v = o1; i1 = oi; }
            else m2v = fmaxf(m2v, o1);
        }
        int idxf = i1;
        float d1 = rcp_approx(m1v);
        float d2 = rcp_approx(m2v);
        if (d2 - d1 <= REFINE_TH) {
            float xr[8];
            #pragma unroll
            for (int k = 0; k < 8; k++) xr[k] = X[(size_t)row*CC + lane + 32*k];
            float thr_iv = rcp_approx(d1 + REFINE_TH) * (1.0f - 2e-6f);
            float bestd = 3.4e38f; int besti = 0x7fffffff;
            for (int j = 0; j < 16; j++) {
                #pragma unroll
                for (int pass = 0; pass < 2; pass++) {
                    float iv = pass ? ivy[j] : ivx[j];
                    unsigned bal = __ballot_sync(0xffffffffu, iv >= thr_iv);
                    while (bal) {
                        int src = __ffs(bal) - 1; bal &= bal - 1;
                        int cidx = 2*(j*32 + src) + pass;
                        const float* er = EMB + (size_t)cidx*CC;
                        float dot = 0.f;
                        #pragma unroll
                        for (int k = 0; k < 8; k++) dot = fmaf(xr[k], er[lane + 32*k], dot);
                        #pragma unroll
                        for (int o = 16; o; o >>= 1) dot += __shfl_xor_sync(0xffffffffu, dot, o);
                        float de = fmaf(-2.f, dot, sA + g_embsq[branch*KCB + cidx]);
                        if (de < bestd || (de == bestd && cidx < besti)) { bestd = de; besti = cidx; }
                    }
                }
            }
            idxf = besti;
        }
        if (lane == 0) {
            g_idx[branch*NN + row] = idxf;
            atomicAdd(&g_hist[branch*KCB + idxf], 1);
        }
        float irs = 1.0f/lsum;
        #pragma unroll
        for (int j = 0; j < 16; j++) { accx[j] += ivx[j]*irs; accy[j] += ivy[j]*irs; }
    }
    #pragma unroll
    for (int j = 0; j < 16; j++) {
        swarp[w][j*64 + 2*lane]     = accx[j];
        swarp[w][j*64 + 2*lane + 1] = accy[j];
    }
    __syncthreads();
    for (int c = tid; c < 1024; c += 256) {
        float s = 0.f;
        #pragma unroll
        for (int ww = 0; ww < 8; ww++) s += swarp[ww][c];
        atomicAdd(&g_avg[branch*KCB + c], s);
    }
}

__global__ void assemble_kernel(const float* __restrict__ emb_s,
                                const float* __restrict__ emb_t,
                                float* __restrict__ out) {
    __shared__ float tl[32][33];
    __shared__ float mred[256];
    int b = blockIdx.z, c0 = blockIdx.y*32, s0 = blockIdx.x*32;
    int tx = threadIdx.x, ty = threadIdx.y;
    float lm = 0.f;
    #pragma unroll
    for (int i = 0; i < 4; i++) {
        int th = s0 + ty + i*8;
        int p = b*THW + th;
        int is = g_idx[p], it = g_idx[NN + p];
        int c = c0 + tx;
        float zpv = g_zp[(size_t)p*CC + c];
        float zq  = emb_t[(size_t)it*CC + c] + emb_s[(size_t)is*CC + c];
        float d = zq - zpv;
        lm += d*d;
        tl[ty + i*8][tx] = zpv + d;
    }
    int tid = ty*32 + tx;
    mred[tid] = lm;
    __syncthreads();
    for (int s = 128; s; s >>= 1) { if (tid < s) mred[tid] += mred[tid+s]; __syncthreads(); }
    if (tid == 0) atomicAdd(&g_mse, (double)mred[0]);
    #pragma unroll
    for (int i = 0; i < 4; i++) {
        int c  = c0 + ty + i*8;
        int th = s0 + tx;
        out[((size_t)(b*CC + c))*THW + th] = tl[tx][ty + i*8];
    }
}

__global__ void ind_write_kernel(float* __restrict__ out) {
    int gid = blockIdx.x*256 + threadIdx.x;
    int br = gid >> 16;
    int o  = gid & (NN - 1);
    int b = o / (TT*HWp);
    int rem = o - b*(TT*HWp);
    int t = rem / HWp;
    int s = rem & (HWp - 1);
    int src = (t*BB + b)*HWp + s;
    out[(br ? OFF_INDT : OFF_INDS) + o] = (float)g_idx[br*NN + src];
}

__global__ void __launch_bounds__(1024) finalize_kernel(float* __restrict__ out) {
    __shared__ double sd[1024];
    int t = threadIdx.x;
    if (t == 0) out[OFF_LOSS] = (float)(1.25 * g_mse / ((double)NN * (double)CC));
    for (int br = 0; br < 2; br++) {
        double e = (double)g_hist[br*KCB + t] / (double)NN;
        sd[t] = e * log(e + 1e-10);
        __syncthreads();
        for (int s = 512; s; s >>= 1) { if (t < s) sd[t] += sd[t+s]; __syncthreads(); }
        if (t == 0) out[br == 0 ? OFF_PERPS : OFF_PERPT] = (float)exp(-sd[0]);
        __syncthreads();
    }
    double kl[2];
    for (int br = 0; br < 2; br++) {
        double a = (double)g_avg[br*KCB + t] / (double)NN;
        sd[t] = a; __syncthreads();
        for (int s = 512; s; s >>= 1) { if (t < s) sd[t] = fmax(sd[t], sd[t+s]); __syncthreads(); }
        double m = sd[0]; __syncthreads();
        sd[t] = exp(a - m); __syncthreads();
        for (int s = 512; s; s >>= 1) { if (t < s) sd[t] += sd[t+s]; __syncthreads(); }
        double Z = sd[0]; __syncthreads();
        sd[t] = a; __syncthreads();
        for (int s = 512; s; s >>= 1) { if (t < s) sd[t] += sd[t+s]; __syncthreads(); }
        double SA = sd[0]; __syncthreads();
        double lse = m + log(Z);
        double tgt = 1.0 / (double)KCB;
        kl[br] = tgt * (log(tgt) + lse - SA / (double)KCB);
    }
    if (t == 0) out[OFF_LOSS2] = (float)(0.1 * (kl[0] + kl[1]));
}

// ================= host =================

extern "C" void kernel_launch(void* const* d_in, const int* in_sizes, int n_in,
                              void* d_out, int out_size) {
    (void)in_sizes; (void)n_in; (void)out_size;
    const float* z     = (const float*)d_in[0];
    const float* emb_s = (const float*)d_in[1];
    const float* emb_t = (const float*)d_in[2];
    const float* gamma = (const float*)d_in[3];
    const float* beta  = (const float*)d_in[4];
    const float* wq = (const float*)d_in[5];
    const float* bq = (const float*)d_in[6];
    const float* wk = (const float*)d_in[7];
    const float* bk = (const float*)d_in[8];
    const float* wv = (const float*)d_in[9];
    const float* bv = (const float*)d_in[10];
    const float* wp = (const float*)d_in[11];
    const float* bp = (const float*)d_in[12];
    float* out = (float*)d_out;

    float *p_zp, *p_q, *p_k, *p_v, *p_embsq, *p_xsq;
    __half *p1h, *p1l, *p2h, *pwh, *pwl, *pebh, *p_dist;
    cudaGetSymbolAddress((void**)&p_zp, g_zp);
    cudaGetSymbolAddress((void**)&p_q,  g_q);
    cudaGetSymbolAddress((void**)&p_k,  g_k);
    cudaGetSymbolAddress((void**)&p_v,  g_v);
    cudaGetSymbolAddress((void**)&p_dist, g_dist);
    cudaGetSymbolAddress((void**)&p_embsq, g_embsq);
    cudaGetSymbolAddress((void**)&p_xsq, g_xsq);
    cudaGetSymbolAddress((void**)&p1h, g_p1h);
    cudaGetSymbolAddress((void**)&p1l, g_p1l);
    cudaGetSymbolAddress((void**)&p2h, g_p2h);
    cudaGetSymbolAddress((void**)&pwh, g_wh);
    cudaGetSymbolAddress((void**)&pwl, g_wl);
    cudaGetSymbolAddress((void**)&pebh, g_ebh);

    cudaFuncSetAttribute(gemm3fp16, cudaFuncAttributeMaxDynamicSharedMemorySize, GSM3);
    cudaFuncSetAttribute(gemm_dist, cudaFuncAttributeMaxDynamicSharedMemorySize, GSM1);

    zero_kernel<<<512, 256>>>();
    embsplit_kernel<<<2*KCB, 256>>>(emb_s, emb_t);
    wsplit_kernel<<<4*CC*CC/256, 256>>>(wq, wk, wv, wp);
    gn_partial<<<2048, 256>>>(z);
    gn_final<<<1, 64>>>();
    transpose_norm_kernel<<<dim3(THW/32, CC/32, BB), dim3(32, 8)>>>(z, gamma, beta);

    // q, k, v convs
    gemm3fp16<<<dim3(CC/128, NN/128), 256, GSM3>>>(p1h, p1l, pwh,           pwl,           bq,
                                                   nullptr, nullptr, nullptr, 0, p_q, CC, ALPHA_CONV);
    gemm3fp16<<<dim3(CC/128, NN/128), 256, GSM3>>>(p1h, p1l, pwh + CC*CC,   pwl + CC*CC,   bk,
                                                   nullptr, nullptr, nullptr, 0, p_k, CC, ALPHA_CONV);
    gemm3fp16<<<dim3(CC/128, NN/128), 256, GSM3>>>(p1h, p1l, pwh + 2*CC*CC, pwl + 2*CC*CC, bv,
                                                   nullptr, nullptr, nullptr, 0, p_v, CC, ALPHA_CONV);

    attn_kernel<<<BB*HWp, 256>>>();
    // proj conv fused with add_diff: writes g_q (ztf), p1h, xsq[branch 1]
    gemm3fp16<<<dim3(CC/128, NN/128), 256, GSM3>>>(p1h, p1l, pwh + 3*CC*CC, pwl + 3*CC*CC, bp,
                                                   p_zp, p_xsq + NN, p1h, 1, p_q, CC, ALPHA_CONV);

    // spatial VQ
    gemm_dist<<<dim3(KCB/128, NN/128), 256, GSM1>>>(p2h, pebh, p_embsq, p_dist, KCB, ALPHA_DIST);
    vq_reduce_kernel<<<NN/64, 256>>>(0, p_zp, emb_s);

    // temporal VQ
    gemm_dist<<<dim3(KCB/128, NN/128), 256, GSM1>>>(p1h, pebh + (size_t)KCB*CC, p_embsq + KCB,
                                                    p_dist, KCB, ALPHA_DIST);
    vq_reduce_kernel<<<NN/64, 256>>>(1, p_q, emb_t);

    assemble_kernel<<<dim3(THW/32, CC/32, BB), dim3(32, 8)>>>(emb_s, emb_t, out);
    ind_write_kernel<<<2*NN/256, 256>>>(out);
    finalize_kernel<<<1, 1024>>>(out);
}

// round 9
// speedup vs baseline: 1.0198x; 1.0198x over previous
#include <cuda_runtime.h>
#include <cuda_fp16.h>
#include <math.h>
#include <cstdint>

#define BB 4
#define CC 256
#define TT 16
#define HH 32
#define WW 32
#define KCB 1024
#define GG 16
#define HWp (HH*WW)          // 1024
#define THW (TT*HWp)         // 16384
#define NN (BB*THW)          // 65536
#define EPSV 1e-6f

#define SXV 64.0f
#define SWV 64.0f
#define SEV 16384.0f
#define ALPHA_CONV (1.0f/(64.0f*64.0f))
#define ALPHA_DIST (-2.0f/(64.0f*16384.0f))
#define REFINE_TH 2e-4f

// ---- output layout ----
#define SZ_ZQ     (BB*CC*THW)
#define OFF_LOSS  (SZ_ZQ)
#define OFF_LOSS2 (SZ_ZQ+1)
#define OFF_INDS  (SZ_ZQ+2)
#define OFF_INDT  (OFF_INDS+NN)
#define OFF_PERPS (OFF_INDT+NN)
#define OFF_PERPT (OFF_PERPS+1)

// ---- scratch ----
__device__ float g_zp[NN*CC];
__device__ float g_q [NN*CC];          // ztf fp32 (proj-fused output)
__device__ float g_qkv[NN*3*CC];       // packed q|k|v, ld=768
__device__ __half g_dist_s[NN*KCB];    // spatial  s = embsq - 2 x.e (fp16)
__device__ __half g_dist_t[NN*KCB];    // temporal s
__device__ __half g_p1h[NN*CC];
__device__ __half g_p1l[NN*CC];
__device__ __half g_p2h[NN*CC];
__device__ __half g_wh[4*CC*CC];
__device__ __half g_wl[4*CC*CC];
__device__ __half g_ebh[2*KCB*CC];
__device__ float g_bias[4*CC];         // bq|bk|bv|bp
__device__ float g_xsq[2*NN];
__device__ float g_embsq[2*KCB];
__device__ double g_sumd[2*BB*GG];
__device__ int   g_idx[2*NN];
__device__ float g_avg[2*KCB];
__device__ int   g_hist[2*KCB];
__device__ double g_mse;

// ================= helpers =================
__device__ __forceinline__ uint32_t smem_u32(const void* p) {
    uint32_t a;
    asm("{ .reg .u64 t; cvta.to.shared.u64 t, %1; cvt.u32.u64 %0, t; }" : "=r"(a) : "l"(p));
    return a;
}
__device__ __forceinline__ float rcp_approx(float x) {
    float r;
    asm("rcp.approx.ftz.f32 %0, %1;" : "=f"(r) : "f"(x));
    return r;
}
#define CP_ASYNC16(dst, src) \
    asm volatile("cp.async.cg.shared.global [%0], [%1], 16;" :: "r"(dst), "l"(src))
#define CP_COMMIT() asm volatile("cp.async.commit_group;" ::: "memory")
#define CP_WAIT1()  asm volatile("cp.async.wait_group 1;" ::: "memory")

__device__ __forceinline__ void ldsm_x4(uint32_t* r, uint32_t addr) {
    asm volatile("ldmatrix.sync.aligned.m8n8.x4.shared.b16 {%0,%1,%2,%3}, [%4];"
        : "=r"(r[0]), "=r"(r[1]), "=r"(r[2]), "=r"(r[3]) : "r"(addr));
}
__device__ __forceinline__ void mma16816(float* d, const uint32_t* a, const uint32_t* b) {
    asm volatile("mma.sync.aligned.m16n8k16.row.col.f32.f16.f16.f32 "
        "{%0,%1,%2,%3}, {%4,%5,%6,%7}, {%8,%9}, {%0,%1,%2,%3};"
        : "+f"(d[0]), "+f"(d[1]), "+f"(d[2]), "+f"(d[3])
        : "r"(a[0]), "r"(a[1]), "r"(a[2]), "r"(a[3]), "r"(b[0]), "r"(b[1]));
}
// fp16-accumulated variant (2x rate path) for the small correction terms
__device__ __forceinline__ void mma16816h(uint32_t* d, const uint32_t* a, const uint32_t* b) {
    asm volatile("mma.sync.aligned.m16n8k16.row.col.f16.f16.f16.f16 "
        "{%0,%1}, {%2,%3,%4,%5}, {%6,%7}, {%0,%1};"
        : "+r"(d[0]), "+r"(d[1])
        : "r"(a[0]), "r"(a[1]), "r"(a[2]), "r"(a[3]), "r"(b[0]), "r"(b[1]));
}
__device__ __forceinline__ void split16(float v, __half* hp, __half* lp) {
    __half h = __float2half_rn(v);
    *hp = h;
    *lp = __float2half_rn(v - __half2float(h));
}

// ================= small kernels =================

__global__ void zero_kernel() {
    int i = blockIdx.x*256 + threadIdx.x;   // grid 512
    if (i < 2*KCB) { g_avg[i] = 0.f; g_hist[i] = 0; }
    if (i < 2*BB*GG) g_sumd[i] = 0.0;
    if (i == 0) g_mse = 0.0;
    g_xsq[i] = 0.f;
}

__global__ void embsplit_kernel(const float* __restrict__ es, const float* __restrict__ et) {
    int row = blockIdx.x, c = threadIdx.x;
    const float* src = (row < KCB) ? (es + (size_t)row*CC) : (et + (size_t)(row-KCB)*CC);
    float v = src[c];
    g_ebh[(size_t)row*CC + c] = __float2half_rn(v*SEV);
    float s = v*v;
    #pragma unroll
    for (int off = 16; off; off >>= 1) s += __shfl_xor_sync(0xffffffffu, s, off);
    __shared__ float red[8];
    if ((c & 31) == 0) red[c >> 5] = s;
    __syncthreads();
    if (c == 0) {
        float t = 0.f;
        #pragma unroll
        for (int j = 0; j < 8; j++) t += red[j];
        g_embsq[row] = t;
    }
}

__global__ void wsplit_kernel(const float* __restrict__ wq, const float* __restrict__ wk,
                              const float* __restrict__ wv, const float* __restrict__ wp,
                              const float* __restrict__ bq, const float* __restrict__ bk,
                              const float* __restrict__ bv, const float* __restrict__ bp) {
    int i = blockIdx.x*256 + threadIdx.x;
    int seg = i >> 16, j = i & 65535;
    const float* src = seg == 0 ? wq : seg == 1 ? wk : seg == 2 ? wv : wp;
    split16(src[j]*SWV, &g_wh[i], &g_wl[i]);
    if (i < 4*CC) {
        int bs = i >> 8, bc = i & 255;
        const float* b = bs == 0 ? bq : bs == 1 ? bk : bs == 2 ? bv : bp;
        g_bias[i] = b[bc];
    }
}

__global__ void __launch_bounds__(256) gn_partial(const float* __restrict__ z) {
    int blk = blockIdx.x;
    int bg = blk >> 5, chunk = blk & 31;
    const float4* p = (const float4*)(z + (size_t)bg*(16*THW) + (size_t)chunk*8192);
    float s = 0.f, s2 = 0.f;
    #pragma unroll
    for (int i = 0; i < 8; i++) {
        float4 v = p[threadIdx.x + i*256];
        s  += v.x + v.y + v.z + v.w;
        s2 += v.x*v.x + v.y*v.y + v.z*v.z + v.w*v.w;
    }
    __shared__ float ss[256], ss2[256];
    ss[threadIdx.x] = s; ss2[threadIdx.x] = s2;
    __syncthreads();
    for (int k = 128; k; k >>= 1) {
        if (threadIdx.x < k) { ss[threadIdx.x] += ss[threadIdx.x+k]; ss2[threadIdx.x] += ss2[threadIdx.x+k]; }
        __syncthreads();
    }
    if (threadIdx.x == 0) {
        atomicAdd(&g_sumd[bg], (double)ss[0]);
        atomicAdd(&g_sumd[64 + bg], (double)ss2[0]);
    }
}

// transpose + groupnorm (stats inlined from g_sumd) + fused xsq[branch 0]
__global__ void transpose_norm_kernel(const float* __restrict__ z,
                                      const float* __restrict__ gamma,
                                      const float* __restrict__ beta) {
    __shared__ float tl[32][33];
    int b = blockIdx.z, c0 = blockIdx.y*32, s0 = blockIdx.x*32;
    int tx = threadIdx.x, ty = threadIdx.y;
    int c = c0 + tx;
    int bg = b*GG + (c >> 4);
    double cnt = (double)(16*THW);
    double mud = g_sumd[bg]/cnt;
    float mu = (float)mud;
    float rstd = rsqrtf((float)(g_sumd[64+bg]/cnt - mud*mud) + EPSV);
    float gam = gamma[c], bet = beta[c];
    #pragma unroll
    for (int i = 0; i < 4; i++) {
        int cc = c0 + ty + i*8;
        tl[ty + i*8][tx] = z[((size_t)(b*CC + cc))*THW + s0 + tx];
    }
    __syncthreads();
    #pragma unroll
    for (int i = 0; i < 4; i++) {
        int th = s0 + ty + i*8;
        float v = tl[tx][ty + i*8];
        size_t o = ((size_t)(b*THW + th))*CC + c;
        g_zp[o] = v;
        g_p2h[o] = __float2half_rn(v*SXV);
        float hn = (v - mu) * rstd * gam + bet;
        split16(hn*SXV, &g_p1h[o], &g_p1l[o]);
        float sq = v*v;
        #pragma unroll
        for (int off = 16; off; off >>= 1) sq += __shfl_xor_sync(0xffffffffu, sq, off);
        if (tx == 0) atomicAdd(&g_xsq[b*THW + th], sq);
    }
}

// ================= HMMA GEMMs =================
#define PITCH 80
#define TILE_B (128*PITCH)
#define STAGE3_B (4*TILE_B)
#define GSM3 (2*STAGE3_B)     // 81920
#define STAGE1_B (2*TILE_B)
#define GSM1 (2*STAGE1_B)     // 40960

__device__ __forceinline__ void g_load_stage3(
        uint32_t sb, int stage, int kc,
        const __half* Ah, const __half* Al,
        const __half* Bh, const __half* Bl,
        int row0, int col0, int tid) {
    int k0 = kc*32;
    uint32_t sbase = sb + stage*STAGE3_B;
    #pragma unroll
    for (int j = 0; j < 8; j++) {
        int idx = j*256 + tid;
        int t = idx >> 9;
        int r = (idx >> 2) & 127;
        int s = idx & 3;
        const __half* gsrc;
        if (t < 2) gsrc = (t ? Al : Ah) + (size_t)(row0 + r)*CC + k0 + s*8;
        else       gsrc = (t == 2 ? Bh : Bl) + (size_t)(col0 + r)*CC + k0 + s*8;
        uint32_t dst = sbase + t*TILE_B + r*PITCH + s*16;
        CP_ASYNC16(dst, gsrc);
    }
}

// conv GEMM: f32-acc main pass + two f16-acc correction passes.
// fuse!=0: proj path -> ztf = out + diff(zp), writes fp32 Out, p1h, xsq partials.
__global__ void __launch_bounds__(256)
gemm3fp16(const __half* __restrict__ Ah, const __half* __restrict__ Al,
          const __half* __restrict__ Bh, const __half* __restrict__ Bl,
          const float* __restrict__ colv,
          const float* __restrict__ zp, float* __restrict__ xsqout,
          __half* __restrict__ p1hout, int fuse,
          float* __restrict__ Out, int out_ld, float alpha) {
    extern __shared__ char smem[];
    uint32_t sb = smem_u32(smem);
    int tid = threadIdx.x, wid = tid >> 5, lane = tid & 31;
    int row0 = blockIdx.y * 128, col0 = blockIdx.x * 128;
    int m_base = (wid & 3) * 32;
    int n_base = (wid >> 2) * 64;

    float acc[2][8][4];
    uint32_t hacc[2][8][2];
    #pragma unroll
    for (int mt = 0; mt < 2; mt++)
        #pragma unroll
        for (int nt = 0; nt < 8; nt++) {
            #pragma unroll
            for (int i = 0; i < 4; i++) acc[mt][nt][i] = 0.f;
            hacc[mt][nt][0] = 0u; hacc[mt][nt][1] = 0u;
        }

    uint32_t a_roff = (uint32_t)(m_base + (lane & 15)) * PITCH + ((lane >> 4) * 16);
    uint32_t b_roff = (uint32_t)(n_base + ((lane >> 4) * 8) + (lane & 7)) * PITCH + (((lane >> 3) & 1) * 16);

    g_load_stage3(sb, 0, 0, Ah, Al, Bh, Bl, row0, col0, tid);
    CP_COMMIT();

    for (int kc = 0; kc < 8; kc++) {
        if (kc + 1 < 8) g_load_stage3(sb, (kc+1) & 1, kc+1, Ah, Al, Bh, Bl, row0, col0, tid);
        CP_COMMIT();
        CP_WAIT1();
        __syncthreads();
        uint32_t st = sb + (kc & 1)*STAGE3_B;
        #pragma unroll
        for (int ks = 0; ks < 2; ks++) {
            uint32_t koff = ks * 32;
            uint32_t ah[2][4], al[2][4], bh[8][2], bl[8][2];
            #pragma unroll
            for (int mt = 0; mt < 2; mt++) {
                uint32_t ad = st + a_roff + (uint32_t)mt*16*PITCH + koff;
                ldsm_x4(ah[mt], ad);
                ldsm_x4(al[mt], ad + TILE_B);
            }
            #pragma unroll
            for (int p = 0; p < 4; p++) {
                uint32_t r4[4];
                uint32_t bd = st + 2*TILE_B + b_roff + (uint32_t)p*16*PITCH + koff;
                ldsm_x4(r4, bd);
                bh[2*p][0] = r4[0]; bh[2*p][1] = r4[1];
                bh[2*p+1][0] = r4[2]; bh[2*p+1][1] = r4[3];
                ldsm_x4(r4, bd + TILE_B);
                bl[2*p][0] = r4[0]; bl[2*p][1] = r4[1];
                bl[2*p+1][0] = r4[2]; bl[2*p+1][1] = r4[3];
            }
            #pragma unroll
            for (int mt = 0; mt < 2; mt++)
                #pragma unroll
                for (int nt = 0; nt < 8; nt++) {
                    mma16816(acc[mt][nt], ah[mt], bh[nt]);
                    mma16816h(hacc[mt][nt], ah[mt], bl[nt]);
                    mma16816h(hacc[mt][nt], al[mt], bh[nt]);
                }
        }
        __syncthreads();
    }

    int g = lane >> 2, t4 = lane & 3;
    if (!fuse) {
        #pragma unroll
        for (int mt = 0; mt < 2; mt++) {
            int r_lo = row0 + m_base + mt*16 + g;
            int r_hi = r_lo + 8;
            #pragma unroll
            for (int nt = 0; nt < 8; nt++) {
                int c = col0 + n_base + nt*8 + 2*t4;
                float2 h01 = __half22float2(*(__half2*)&hacc[mt][nt][0]);
                float2 h23 = __half22float2(*(__half2*)&hacc[mt][nt][1]);
                float cv0 = colv[c], cv1 = colv[c+1];
                *(float2*)(Out + (size_t)r_lo*out_ld + c) =
                    make_float2(fmaf(alpha, acc[mt][nt][0] + h01.x, cv0),
                                fmaf(alpha, acc[mt][nt][1] + h01.y, cv1));
                *(float2*)(Out + (size_t)r_hi*out_ld + c) =
                    make_float2(fmaf(alpha, acc[mt][nt][2] + h23.x, cv0),
                                fmaf(alpha, acc[mt][nt][3] + h23.y, cv1));
            }
        }
    } else {
        #pragma unroll
        for (int mt = 0; mt < 2; mt++) {
            #pragma unroll
            for (int half_i = 0; half_i < 2; half_i++) {
                int r = row0 + m_base + mt*16 + g + half_i*8;
                int t = (r >> 10) & 15;
                float sq = 0.f;
                #pragma unroll
                for (int nt = 0; nt < 8; nt++) {
                    int c = col0 + n_base + nt*8 + 2*t4;
                    size_t idx = (size_t)r*out_ld + c;
                    float2 zc = *(const float2*)(zp + idx);
                    float2 zm = t ? *(const float2*)(zp + idx - (size_t)HWp*CC) : zc;
                    float2 hc = __half22float2(*(__half2*)&hacc[mt][nt][half_i]);
                    float a0 = (half_i ? acc[mt][nt][2] : acc[mt][nt][0]) + hc.x;
                    float a1 = (half_i ? acc[mt][nt][3] : acc[mt][nt][1]) + hc.y;
                    float v0 = fmaf(alpha, a0, colv[c])   + (zc.x - zm.x);
                    float v1 = fmaf(alpha, a1, colv[c+1]) + (zc.y - zm.y);
                    *(float2*)(Out + idx) = make_float2(v0, v1);
                    *(__half2*)(p1hout + idx) = __floats2half2_rn(v0*SXV, v1*SXV);
                    sq += v0*v0 + v1*v1;
                }
                sq += __shfl_xor_sync(0xffffffffu, sq, 1);
                sq += __shfl_xor_sync(0xffffffffu, sq, 2);
                if (t4 == 0) atomicAdd(&xsqout[r], sq);
            }
        }
    }
}

// single-pass dist GEMM (fp32 acc); stores s = embsq[c] - 2 x.e as fp16
__device__ __forceinline__ void g_load_stage1(
        uint32_t sb, int stage, int kc,
        const __half* Ah, const __half* Bh,
        int row0, int col0, int tid) {
    int k0 = kc*32;
    uint32_t sbase = sb + stage*STAGE1_B;
    #pragma unroll
    for (int j = 0; j < 4; j++) {
        int idx = j*256 + tid;
        int t = idx >> 9;
        int r = (idx >> 2) & 127;
        int s = idx & 3;
        const __half* gsrc = (t ? Bh + (size_t)(col0 + r)*CC : Ah + (size_t)(row0 + r)*CC) + k0 + s*8;
        uint32_t dst = sbase + t*TILE_B + r*PITCH + s*16;
        CP_ASYNC16(dst, gsrc);
    }
}

__global__ void __launch_bounds__(256)
gemm_dist(const __half* __restrict__ Ah, const __half* __restrict__ Bh,
          const float* __restrict__ colv,
          __half* __restrict__ OutH, int out_ld, float alpha) {
    extern __shared__ char smem[];
    uint32_t sb = smem_u32(smem);
    int tid = threadIdx.x, wid = tid >> 5, lane = tid & 31;
    int row0 = blockIdx.y * 128, col0 = blockIdx.x * 128;
    int m_base = (wid & 3) * 32;
    int n_base = (wid >> 2) * 64;

    float acc[2][8][4];
    #pragma unroll
    for (int mt = 0; mt < 2; mt++)
        #pragma unroll
        for (int nt = 0; nt < 8; nt++)
            #pragma unroll
            for (int i = 0; i < 4; i++) acc[mt][nt][i] = 0.f;

    uint32_t a_roff = (uint32_t)(m_base + (lane & 15)) * PITCH + ((lane >> 4) * 16);
    uint32_t b_roff = (uint32_t)(n_base + ((lane >> 4) * 8) + (lane & 7)) * PITCH + (((lane >> 3) & 1) * 16);

    g_load_stage1(sb, 0, 0, Ah, Bh, row0, col0, tid);
    CP_COMMIT();

    for (int kc = 0; kc < 8; kc++) {
        if (kc + 1 < 8) g_load_stage1(sb, (kc+1) & 1, kc+1, Ah, Bh, row0, col0, tid);
        CP_COMMIT();
        CP_WAIT1();
        __syncthreads();
        uint32_t st = sb + (kc & 1)*STAGE1_B;
        #pragma unroll
        for (int ks = 0; ks < 2; ks++) {
            uint32_t koff = ks * 32;
            uint32_t ah[2][4], bh[8][2];
            #pragma unroll
            for (int mt = 0; mt < 2; mt++)
                ldsm_x4(ah[mt], st + a_roff + (uint32_t)mt*16*PITCH + koff);
            #pragma unroll
            for (int p = 0; p < 4; p++) {
                uint32_t r4[4];
                ldsm_x4(r4, st + TILE_B + b_roff + (uint32_t)p*16*PITCH + koff);
                bh[2*p][0] = r4[0]; bh[2*p][1] = r4[1];
                bh[2*p+1][0] = r4[2]; bh[2*p+1][1] = r4[3];
            }
            #pragma unroll
            for (int mt = 0; mt < 2; mt++)
                #pragma unroll
                for (int nt = 0; nt < 8; nt++)
                    mma16816(acc[mt][nt], ah[mt], bh[nt]);
        }
        __syncthreads();
    }

    int g = lane >> 2, t4 = lane & 3;
    #pragma unroll
    for (int mt = 0; mt < 2; mt++) {
        int r_lo = row0 + m_base + mt*16 + g;
        int r_hi = r_lo + 8;
        #pragma unroll
        for (int nt = 0; nt < 8; nt++) {
            int c = col0 + n_base + nt*8 + 2*t4;
            float cv0 = colv[c], cv1 = colv[c+1];
            *(__half2*)(OutH + (size_t)r_lo*out_ld + c) =
                __floats2half2_rn(fmaf(alpha, acc[mt][nt][0], cv0), fmaf(alpha, acc[mt][nt][1], cv1));
            *(__half2*)(OutH + (size_t)r_hi*out_ld + c) =
                __floats2half2_rn(fmaf(alpha, acc[mt][nt][2], cv0), fmaf(alpha, acc[mt][nt][3], cv1));
        }
    }
}

// ================= attention (reads packed qkv, ld=768) =================
#define APAD 260
__global__ void __launch_bounds__(256) attn_kernel() {
    __shared__ float qs[16][APAD], ks[16][APAD];
    __shared__ float att[16][16];
    int x = blockIdx.x;
    int b = x >> 10;
    int s = x & (HWp - 1);
    size_t base = ((size_t)(b*TT)*HWp + s)*(3*CC);
    const size_t tstr = (size_t)HWp*(3*CC);
    int tid = threadIdx.x;
    for (int e = tid; e < 16*256; e += 256) {
        int t = e >> 8, c = e & 255;
        qs[t][c] = g_qkv[base + (size_t)t*tstr + c];
        ks[t][c] = g_qkv[base + (size_t)t*tstr + 256 + c];
    }
    __syncthreads();
    int i = tid >> 4, j = tid & 15;
    float acc = 0.f;
    #pragma unroll 8
    for (int c4 = 0; c4 < 64; c4++) {
        float4 a = *(const float4*)&qs[i][c4*4];
        float4 bb = *(const float4*)&ks[j][c4*4];
        acc = fmaf(a.x, bb.x, acc); acc = fmaf(a.y, bb.y, acc);
        acc = fmaf(a.z, bb.z, acc); acc = fmaf(a.w, bb.w, acc);
    }
    att[i][j] = acc * 0.0625f;
    __syncthreads();
    if (tid < 16) {
        float m = -3.4e38f;
        for (int jj = 0; jj < 16; jj++) m = fmaxf(m, att[tid][jj]);
        float ssum = 0.f;
        for (int jj = 0; jj < 16; jj++) { float e = expf(att[tid][jj]-m); att[tid][jj] = e; ssum += e; }
        float r = 1.0f/ssum;
        for (int jj = 0; jj < 16; jj++) att[tid][jj] *= r;
    }
    __syncthreads();
    int c = tid;
    float vv[16];
    #pragma unroll
    for (int tk = 0; tk < 16; tk++) vv[tk] = g_qkv[base + (size_t)tk*tstr + 512 + c];
    size_t obase = ((size_t)(b*TT)*HWp + s)*CC;
    const size_t otstr = (size_t)HWp*CC;
    #pragma unroll
    for (int tq = 0; tq < 16; tq++) {
        float o = 0.f;
        #pragma unroll
        for (int tk = 0; tk < 16; tk++) o += att[tq][tk]*vv[tk];
        size_t oi = obase + (size_t)tq*otstr + c;
        split16(o*SXV, &g_p1h[oi], &g_p1l[oi]);
    }
}

// warp-per-row reduce: d = xsq[row] + s(fp16); iv = rcp(d); argmax iv + refine; avg
__global__ void __launch_bounds__(256) vq_reduce_kernel(int branch, const __half* __restrict__ DIST,
                                                        const float* __restrict__ X,
                                                        const float* __restrict__ EMB) {
    __shared__ float swarp[8][1024];
    int tid = threadIdx.x, w = tid >> 5, lane = tid & 31;
    int row0 = blockIdx.x * 64;
    float accx[16], accy[16];
    #pragma unroll
    for (int j = 0; j < 16; j++) { accx[j] = 0.f; accy[j] = 0.f; }
    for (int rr = 0; rr < 8; rr++) {
        int row = row0 + w*8 + rr;
        const __half2* dr = (const __half2*)(DIST + (size_t)row*KCB);
        float sA = g_xsq[branch*NN + row];
        float ivx[16], ivy[16];
        float lsum = 0.f, m1v = 0.f, m2v = 0.f; int i1 = 0;
        #pragma unroll
        for (int j = 0; j < 16; j++) {
            float2 s2 = __half22float2(dr[j*32 + lane]);
            float ix = rcp_approx(sA + s2.x);
            float iy = rcp_approx(sA + s2.y);
            ivx[j] = ix; ivy[j] = iy; lsum += ix + iy;
            int cb = 2*(j*32 + lane);
            if (ix > m1v) { m2v = m1v; m1v = ix; i1 = cb; } else m2v = fmaxf(m2v, ix);
            if (iy > m1v) { m2v = m1v; m1v = iy; i1 = cb+1; } else m2v = fmaxf(m2v, iy);
        }
        #pragma unroll
        for (int o = 16; o; o >>= 1) {
            lsum += __shfl_xor_sync(0xffffffffu, lsum, o);
            float o1 = __shfl_xor_sync(0xffffffffu, m1v, o);
            int   oi = __shfl_xor_sync(0xffffffffu, i1, o);
            float o2 = __shfl_xor_sync(0xffffffffu, m2v, o);
            if (o1 > m1v || (o1 == m1v && oi < i1)) { m2v = fmaxf(m1v, o2); m1v = o1; i1 = oi; }
            else m2v = fmaxf(m2v, o1);
        }
        int idxf = i1;
        float d1 = rcp_approx(m1v);
        float d2 = rcp_approx(m2v);
        if (d2 - d1 <= REFINE_TH) {
            float xr[8];
            #pragma unroll
            for (int k = 0; k < 8; k++) xr[k] = X[(size_t)row*CC + lane + 32*k];
            float thr_iv = rcp_approx(d1 + REFINE_TH) * (1.0f - 2e-6f);
            float bestd = 3.4e38f; int besti = 0x7fffffff;
            for (int j = 0; j < 16; j++) {
                #pragma unroll
                for (int pass = 0; pass < 2; pass++) {
                    float iv = pass ? ivy[j] : ivx[j];
                    unsigned bal = __ballot_sync(0xffffffffu, iv >= thr_iv);
                    while (bal) {
                        int src = __ffs(bal) - 1; bal &= bal - 1;
                        int cidx = 2*(j*32 + src) + pass;
                        const float* er = EMB + (size_t)cidx*CC;
                        float dot = 0.f;
                        #pragma unroll
                        for (int k = 0; k < 8; k++) dot = fmaf(xr[k], er[lane + 32*k], dot);
                        #pragma unroll
                        for (int o = 16; o; o >>= 1) dot += __shfl_xor_sync(0xffffffffu, dot, o);
                        float de = fmaf(-2.f, dot, sA + g_embsq[branch*KCB + cidx]);
                        if (de < bestd || (de == bestd && cidx < besti)) { bestd = de; besti = cidx; }
                    }
                }
            }
            idxf = besti;
        }
        if (lane == 0) {
            g_idx[branch*NN + row] = idxf;
            atomicAdd(&g_hist[branch*KCB + idxf], 1);
        }
        float irs = 1.0f/lsum;
        #pragma unroll
        for (int j = 0; j < 16; j++) { accx[j] += ivx[j]*irs; accy[j] += ivy[j]*irs; }
    }
    #pragma unroll
    for (int j = 0; j < 16; j++) {
        swarp[w][j*64 + 2*lane]     = accx[j];
        swarp[w][j*64 + 2*lane + 1] = accy[j];
    }
    __syncthreads();
    for (int c = tid; c < 1024; c += 256) {
        float s = 0.f;
        #pragma unroll
        for (int ww = 0; ww < 8; ww++) s += swarp[ww][c];
        atomicAdd(&g_avg[branch*KCB + c], s);
    }
}

__global__ void assemble_kernel(const float* __restrict__ emb_s,
                                const float* __restrict__ emb_t,
                                float* __restrict__ out) {
    __shared__ float tl[32][33];
    __shared__ float mred[256];
    int b = blockIdx.z, c0 = blockIdx.y*32, s0 = blockIdx.x*32;
    int tx = threadIdx.x, ty = threadIdx.y;
    float lm = 0.f;
    #pragma unroll
    for (int i = 0; i < 4; i++) {
        int th = s0 + ty + i*8;
        int p = b*THW + th;
        int is = g_idx[p], it = g_idx[NN + p];
        int c = c0 + tx;
        float zpv = g_zp[(size_t)p*CC + c];
        float zq  = emb_t[(size_t)it*CC + c] + emb_s[(size_t)is*CC + c];
        float d = zq - zpv;
        lm += d*d;
        tl[ty + i*8][tx] = zpv + d;
    }
    int tid = ty*32 + tx;
    mred[tid] = lm;
    __syncthreads();
    for (int s = 128; s; s >>= 1) { if (tid < s) mred[tid] += mred[tid+s]; __syncthreads(); }
    if (tid == 0) atomicAdd(&g_mse, (double)mred[0]);
    #pragma unroll
    for (int i = 0; i < 4; i++) {
        int c  = c0 + ty + i*8;
        int th = s0 + tx;
        out[((size_t)(b*CC + c))*THW + th] = tl[tx][ty + i*8];
    }
}

__global__ void ind_write_kernel(float* __restrict__ out) {
    int gid = blockIdx.x*256 + threadIdx.x;
    int br = gid >> 16;
    int o  = gid & (NN - 1);
    int b = o / (TT*HWp);
    int rem = o - b*(TT*HWp);
    int t = rem / HWp;
    int s = rem & (HWp - 1);
    int src = (t*BB + b)*HWp + s;
    out[(br ? OFF_INDT : OFF_INDS) + o] = (float)g_idx[br*NN + src];
}

__global__ void __launch_bounds__(1024) finalize_kernel(float* __restrict__ out) {
    __shared__ double sd[1024];
    int t = threadIdx.x;
    if (t == 0) out[OFF_LOSS] = (float)(1.25 * g_mse / ((double)NN * (double)CC));
    for (int br = 0; br < 2; br++) {
        double e = (double)g_hist[br*KCB + t] / (double)NN;
        sd[t] = e * log(e + 1e-10);
        __syncthreads();
        for (int s = 512; s; s >>= 1) { if (t < s) sd[t] += sd[t+s]; __syncthreads(); }
        if (t == 0) out[br == 0 ? OFF_PERPS : OFF_PERPT] = (float)exp(-sd[0]);
        __syncthreads();
    }
    double kl[2];
    for (int br = 0; br < 2; br++) {
        double a = (double)g_avg[br*KCB + t] / (double)NN;
        sd[t] = a; __syncthreads();
        for (int s = 512; s; s >>= 1) { if (t < s) sd[t] = fmax(sd[t], sd[t+s]); __syncthreads(); }
        double m = sd[0]; __syncthreads();
        sd[t] = exp(a - m); __syncthreads();
        for (int s = 512; s; s >>= 1) { if (t < s) sd[t] += sd[t+s]; __syncthreads(); }
        double Z = sd[0]; __syncthreads();
        sd[t] = a; __syncthreads();
        for (int s = 512; s; s >>= 1) { if (t < s) sd[t] += sd[t+s]; __syncthreads(); }
        double SA = sd[0]; __syncthreads();
        double lse = m + log(Z);
        double tgt = 1.0 / (double)KCB;
        kl[br] = tgt * (log(tgt) + lse - SA / (double)KCB);
    }
    if (t == 0) out[OFF_LOSS2] = (float)(0.1 * (kl[0] + kl[1]));
}

// ================= host =================

extern "C" void kernel_launch(void* const* d_in, const int* in_sizes, int n_in,
                              void* d_out, int out_size) {
    (void)in_sizes; (void)n_in; (void)out_size;
    const float* z     = (const float*)d_in[0];
    const float* emb_s = (const float*)d_in[1];
    const float* emb_t = (const float*)d_in[2];
    const float* gamma = (const float*)d_in[3];
    const float* beta  = (const float*)d_in[4];
    const float* wq = (const float*)d_in[5];
    const float* bq = (const float*)d_in[6];
    const float* wk = (const float*)d_in[7];
    const float* bk = (const float*)d_in[8];
    const float* wv = (const float*)d_in[9];
    const float* bv = (const float*)d_in[10];
    const float* wp = (const float*)d_in[11];
    const float* bp = (const float*)d_in[12];
    float* out = (float*)d_out;

    float *p_zp, *p_q, *p_qkv, *p_embsq, *p_xsq, *p_bias;
    __half *p1h, *p1l, *p2h, *pwh, *pwl, *pebh, *pds, *pdt;
    cudaGetSymbolAddress((void**)&p_zp, g_zp);
    cudaGetSymbolAddress((void**)&p_q,  g_q);
    cudaGetSymbolAddress((void**)&p_qkv, g_qkv);
    cudaGetSymbolAddress((void**)&pds, g_dist_s);
    cudaGetSymbolAddress((void**)&pdt, g_dist_t);
    cudaGetSymbolAddress((void**)&p_embsq, g_embsq);
    cudaGetSymbolAddress((void**)&p_xsq, g_xsq);
    cudaGetSymbolAddress((void**)&p_bias, g_bias);
    cudaGetSymbolAddress((void**)&p1h, g_p1h);
    cudaGetSymbolAddress((void**)&p1l, g_p1l);
    cudaGetSymbolAddress((void**)&p2h, g_p2h);
    cudaGetSymbolAddress((void**)&pwh, g_wh);
    cudaGetSymbolAddress((void**)&pwl, g_wl);
    cudaGetSymbolAddress((void**)&pebh, g_ebh);

    static cudaStream_t s2 = nullptr;
    static cudaEvent_t evA, evB, evC, evD;
    if (!s2) {
        cudaStreamCreateWithFlags(&s2, cudaStreamNonBlocking);
        cudaEventCreateWithFlags(&evA, cudaEventDisableTiming);
        cudaEventCreateWithFlags(&evB, cudaEventDisableTiming);
        cudaEventCreateWithFlags(&evC, cudaEventDisableTiming);
        cudaEventCreateWithFlags(&evD, cudaEventDisableTiming);
        cudaFuncSetAttribute(gemm3fp16, cudaFuncAttributeMaxDynamicSharedMemorySize, GSM3);
        cudaFuncSetAttribute(gemm_dist, cudaFuncAttributeMaxDynamicSharedMemorySize, GSM1);
    }

    // stream 0: zero -> gn -> transpose -> [qkv -> attn -> proj -> dist_t -> vq_t]
    // stream s2: embsplit/wsplit ; after transpose: dist_s -> vq_s
    zero_kernel<<<512, 256>>>();
    cudaEventRecord(evA, 0);
    cudaStreamWaitEvent(s2, evA, 0);
    embsplit_kernel<<<2*KCB, 256, 0, s2>>>(emb_s, emb_t);
    wsplit_kernel<<<4*CC*CC/256, 256, 0, s2>>>(wq, wk, wv, wp, bq, bk, bv, bp);
    cudaEventRecord(evB, s2);

    gn_partial<<<2048, 256>>>(z);
    transpose_norm_kernel<<<dim3(THW/32, CC/32, BB), dim3(32, 8)>>>(z, gamma, beta);
    cudaEventRecord(evC, 0);

    // spatial VQ branch on s2 (needs transpose (evC) + embsplit (s2 in-order))
    cudaStreamWaitEvent(s2, evC, 0);
    gemm_dist<<<dim3(KCB/128, NN/128), 256, GSM1, s2>>>(p2h, pebh, p_embsq, pds, KCB, ALPHA_DIST);
    vq_reduce_kernel<<<NN/64, 256, 0, s2>>>(0, pds, p_zp, emb_s);
    cudaEventRecord(evD, s2);

    // temporal chain on stream 0 (needs wsplit)
    cudaStreamWaitEvent(0, evB, 0);
    gemm3fp16<<<dim3(3*CC/128, NN/128), 256, GSM3>>>(p1h, p1l, pwh, pwl, p_bias,
                                                     nullptr, nullptr, nullptr, 0, p_qkv, 3*CC, ALPHA_CONV);
    attn_kernel<<<BB*HWp, 256>>>();
    gemm3fp16<<<dim3(CC/128, NN/128), 256, GSM3>>>(p1h, p1l, pwh + 3*CC*CC, pwl + 3*CC*CC, p_bias + 3*CC,
                                                   p_zp, p_xsq + NN, p1h, 1, p_q, CC, ALPHA_CONV);
    gemm_dist<<<dim3(KCB/128, NN/128), 256, GSM1>>>(p1h, pebh + (size_t)KCB*CC, p_embsq + KCB,
                                                    pdt, KCB, ALPHA_DIST);
    vq_reduce_kernel<<<NN/64, 256>>>(1, pdt, p_q, emb_t);

    // join + outputs
    cudaStreamWaitEvent(0, evD, 0);
    assemble_kernel<<<dim3(THW/32, CC/32, BB), dim3(32, 8)>>>(emb_s, emb_t, out);
    ind_write_kernel<<<2*NN/256, 256>>>(out);
    finalize_kernel<<<1, 1024>>>(out);
}

// round 10
// speedup vs baseline: 1.2062x; 1.1828x over previous
#include <cuda_runtime.h>
#include <cuda_fp16.h>
#include <math.h>
#include <cstdint>

#define BB 4
#define CC 256
#define TT 16
#define HH 32
#define WW 32
#define KCB 1024
#define GG 16
#define HWp (HH*WW)          // 1024
#define THW (TT*HWp)         // 16384
#define NN (BB*THW)          // 65536
#define EPSV 1e-6f

#define SXV 64.0f
#define SWV 64.0f
#define SEV 16384.0f
#define ALPHA_CONV (1.0f/(64.0f*64.0f))
#define ALPHA_DIST (-2.0f/(64.0f*16384.0f))
#define REFINE_TH 2e-4f

// ---- output layout ----
#define SZ_ZQ     (BB*CC*THW)
#define OFF_LOSS  (SZ_ZQ)
#define OFF_LOSS2 (SZ_ZQ+1)
#define OFF_INDS  (SZ_ZQ+2)
#define OFF_INDT  (OFF_INDS+NN)
#define OFF_PERPS (OFF_INDT+NN)
#define OFF_PERPT (OFF_PERPS+1)

// ---- scratch ----
__device__ float g_zp[NN*CC];
__device__ float g_q [NN*CC];          // ztf fp32
__device__ float g_yz[NN*2*CC];        // packed Y|Z per row, ld=512
__device__ __half g_dist_s[NN*KCB];
__device__ __half g_dist_t[NN*KCB];
__device__ __half g_p1h[NN*CC];        // 64*hn hi -> 64*ztf hi (after attn)
__device__ __half g_p1l[NN*CC];        // 64*hn lo
__device__ __half g_p2h[NN*CC];        // 64*zp hi
__device__ __half g_wh[2*CC*CC];       // 64*[M | P] rows: [0,256)=M cols(Y), [256,512)=P cols(Z)
__device__ __half g_wl[2*CC*CC];
__device__ __half g_ebh[2*KCB*CC];
__device__ float g_bias[2*CC];         // [0,256)=u, [256,512)=cvec
__device__ float g_xsq[2*NN];
__device__ float g_embsq[2*KCB];
__device__ double g_sumd[2*BB*GG];
__device__ int   g_idx[2*NN];
__device__ float g_avg[2*KCB];
__device__ int   g_hist[2*KCB];
__device__ double g_mse;

// ================= helpers =================
__device__ __forceinline__ uint32_t smem_u32(const void* p) {
    uint32_t a;
    asm("{ .reg .u64 t; cvta.to.shared.u64 t, %1; cvt.u32.u64 %0, t; }" : "=r"(a) : "l"(p));
    return a;
}
__device__ __forceinline__ float rcp_approx(float x) {
    float r;
    asm("rcp.approx.ftz.f32 %0, %1;" : "=f"(r) : "f"(x));
    return r;
}
#define CP_ASYNC16(dst, src) \
    asm volatile("cp.async.cg.shared.global [%0], [%1], 16;" :: "r"(dst), "l"(src))
#define CP_COMMIT() asm volatile("cp.async.commit_group;" ::: "memory")
#define CP_WAIT1()  asm volatile("cp.async.wait_group 1;" ::: "memory")

__device__ __forceinline__ void ldsm_x4(uint32_t* r, uint32_t addr) {
    asm volatile("ldmatrix.sync.aligned.m8n8.x4.shared.b16 {%0,%1,%2,%3}, [%4];"
        : "=r"(r[0]), "=r"(r[1]), "=r"(r[2]), "=r"(r[3]) : "r"(addr));
}
__device__ __forceinline__ void mma16816(float* d, const uint32_t* a, const uint32_t* b) {
    asm volatile("mma.sync.aligned.m16n8k16.row.col.f32.f16.f16.f32 "
        "{%0,%1,%2,%3}, {%4,%5,%6,%7}, {%8,%9}, {%0,%1,%2,%3};"
        : "+f"(d[0]), "+f"(d[1]), "+f"(d[2]), "+f"(d[3])
        : "r"(a[0]), "r"(a[1]), "r"(a[2]), "r"(a[3]), "r"(b[0]), "r"(b[1]));
}
__device__ __forceinline__ void mma16816h(uint32_t* d, const uint32_t* a, const uint32_t* b) {
    asm volatile("mma.sync.aligned.m16n8k16.row.col.f16.f16.f16.f16 "
        "{%0,%1}, {%2,%3,%4,%5}, {%6,%7}, {%0,%1};"
        : "+r"(d[0]), "+r"(d[1])
        : "r"(a[0]), "r"(a[1]), "r"(a[2]), "r"(a[3]), "r"(b[0]), "r"(b[1]));
}
__device__ __forceinline__ void split16(float v, __half* hp, __half* lp) {
    __half h = __float2half_rn(v);
    *hp = h;
    *lp = __float2half_rn(v - __half2float(h));
}

// ================= small kernels =================

__global__ void zero_kernel() {
    int i = blockIdx.x*256 + threadIdx.x;   // grid 512
    if (i < 2*KCB) { g_avg[i] = 0.f; g_hist[i] = 0; }
    if (i < 2*BB*GG) g_sumd[i] = 0.0;
    if (i == 0) g_mse = 0.0;
    g_xsq[i] = 0.f;
}

__global__ void embsplit_kernel(const float* __restrict__ es, const float* __restrict__ et) {
    int row = blockIdx.x, c = threadIdx.x;
    const float* src = (row < KCB) ? (es + (size_t)row*CC) : (et + (size_t)(row-KCB)*CC);
    float v = src[c];
    g_ebh[(size_t)row*CC + c] = __float2half_rn(v*SEV);
    float s = v*v;
    #pragma unroll
    for (int off = 16; off; off >>= 1) s += __shfl_xor_sync(0xffffffffu, s, off);
    __shared__ float red[8];
    if ((c & 31) == 0) red[c >> 5] = s;
    __syncthreads();
    if (c == 0) {
        float t = 0.f;
        #pragma unroll
        for (int j = 0; j < 8; j++) t += red[j];
        g_embsq[row] = t;
    }
}

// weight-product kernel: M = Wq^T Wk (Y path), P = Wp Wv (Z path), u = Wk^T bq, cvec = Wp bv + bp
__global__ void __launch_bounds__(256) wprod_kernel(
        const float* __restrict__ wq, const float* __restrict__ wk,
        const float* __restrict__ wv, const float* __restrict__ wp,
        const float* __restrict__ bq, const float* __restrict__ bv,
        const float* __restrict__ bp) {
    int blk = blockIdx.x, c = threadIdx.x;
    if (blk < 256) {
        int cout = blk;   // Y output column
        float acc = 0.f, uacc = 0.f;
        for (int o = 0; o < 256; o++) {
            float wkv = wk[o*256 + cout];
            acc = fmaf(wq[o*256 + c], wkv, acc);
            uacc = fmaf(wkv, bq[o], uacc);
        }
        split16(acc*SWV, &g_wh[(size_t)cout*CC + c], &g_wl[(size_t)cout*CC + c]);
        if (c == 0) g_bias[cout] = uacc;
    } else {
        int oo = blk - 256;   // Z output column
        float acc = 0.f, cb = 0.f;
        for (int cm = 0; cm < 256; cm++) {
            float wpv = wp[oo*256 + cm];
            acc = fmaf(wpv, wv[cm*256 + c], acc);
            cb = fmaf(wpv, bv[cm], cb);
        }
        split16(acc*SWV, &g_wh[(size_t)(256 + oo)*CC + c], &g_wl[(size_t)(256 + oo)*CC + c]);
        if (c == 0) g_bias[256 + oo] = cb + bp[oo];
    }
}

__global__ void __launch_bounds__(256) gn_partial(const float* __restrict__ z) {
    int blk = blockIdx.x;
    int bg = blk >> 5, chunk = blk & 31;
    const float4* p = (const float4*)(z + (size_t)bg*(16*THW) + (size_t)chunk*8192);
    float s = 0.f, s2 = 0.f;
    #pragma unroll
    for (int i = 0; i < 8; i++) {
        float4 v = p[threadIdx.x + i*256];
        s  += v.x + v.y + v.z + v.w;
        s2 += v.x*v.x + v.y*v.y + v.z*v.z + v.w*v.w;
    }
    __shared__ float ss[256], ss2[256];
    ss[threadIdx.x] = s; ss2[threadIdx.x] = s2;
    __syncthreads();
    for (int k = 128; k; k >>= 1) {
        if (threadIdx.x < k) { ss[threadIdx.x] += ss[threadIdx.x+k]; ss2[threadIdx.x] += ss2[threadIdx.x+k]; }
        __syncthreads();
    }
    if (threadIdx.x == 0) {
        atomicAdd(&g_sumd[bg], (double)ss[0]);
        atomicAdd(&g_sumd[64 + bg], (double)ss2[0]);
    }
}

// transpose + groupnorm + fused xsq[branch 0]
__global__ void transpose_norm_kernel(const float* __restrict__ z,
                                      const float* __restrict__ gamma,
                                      const float* __restrict__ beta) {
    __shared__ float tl[32][33];
    int b = blockIdx.z, c0 = blockIdx.y*32, s0 = blockIdx.x*32;
    int tx = threadIdx.x, ty = threadIdx.y;
    int c = c0 + tx;
    int bg = b*GG + (c >> 4);
    double cnt = (double)(16*THW);
    double mud = g_sumd[bg]/cnt;
    float mu = (float)mud;
    float rstd = rsqrtf((float)(g_sumd[64+bg]/cnt - mud*mud) + EPSV);
    float gam = gamma[c], bet = beta[c];
    #pragma unroll
    for (int i = 0; i < 4; i++) {
        int cc = c0 + ty + i*8;
        tl[ty + i*8][tx] = z[((size_t)(b*CC + cc))*THW + s0 + tx];
    }
    __syncthreads();
    #pragma unroll
    for (int i = 0; i < 4; i++) {
        int th = s0 + ty + i*8;
        float v = tl[tx][ty + i*8];
        size_t o = ((size_t)(b*THW + th))*CC + c;
        g_zp[o] = v;
        g_p2h[o] = __float2half_rn(v*SXV);
        float hn = (v - mu) * rstd * gam + bet;
        split16(hn*SXV, &g_p1h[o], &g_p1l[o]);
        float sq = v*v;
        #pragma unroll
        for (int off = 16; off; off >>= 1) sq += __shfl_xor_sync(0xffffffffu, sq, off);
        if (tx == 0) atomicAdd(&g_xsq[b*THW + th], sq);
    }
}

// ================= HMMA GEMMs =================
#define PITCH 80
#define TILE_B (128*PITCH)
#define STAGE3_B (4*TILE_B)
#define GSM3 (2*STAGE3_B)     // 81920
#define STAGE1_B (2*TILE_B)
#define GSM1 (2*STAGE1_B)     // 40960

__device__ __forceinline__ void g_load_stage3(
        uint32_t sb, int stage, int kc,
        const __half* Ah, const __half* Al,
        const __half* Bh, const __half* Bl,
        int row0, int col0, int tid) {
    int k0 = kc*32;
    uint32_t sbase = sb + stage*STAGE3_B;
    #pragma unroll
    for (int j = 0; j < 8; j++) {
        int idx = j*256 + tid;
        int t = idx >> 9;
        int r = (idx >> 2) & 127;
        int s = idx & 3;
        const __half* gsrc;
        if (t < 2) gsrc = (t ? Al : Ah) + (size_t)(row0 + r)*CC + k0 + s*8;
        else       gsrc = (t == 2 ? Bh : Bl) + (size_t)(col0 + r)*CC + k0 + s*8;
        uint32_t dst = sbase + t*TILE_B + r*PITCH + s*16;
        CP_ASYNC16(dst, gsrc);
    }
}

// split GEMM: f32-acc main pass + two f16-acc correction passes
__global__ void __launch_bounds__(256)
gemm3fp16(const __half* __restrict__ Ah, const __half* __restrict__ Al,
          const __half* __restrict__ Bh, const __half* __restrict__ Bl,
          const float* __restrict__ colv,
          float* __restrict__ Out, int out_ld, float alpha) {
    extern __shared__ char smem[];
    uint32_t sb = smem_u32(smem);
    int tid = threadIdx.x, wid = tid >> 5, lane = tid & 31;
    int row0 = blockIdx.y * 128, col0 = blockIdx.x * 128;
    int m_base = (wid & 3) * 32;
    int n_base = (wid >> 2) * 64;

    float acc[2][8][4];
    uint32_t hacc[2][8][2];
    #pragma unroll
    for (int mt = 0; mt < 2; mt++)
        #pragma unroll
        for (int nt = 0; nt < 8; nt++) {
            #pragma unroll
            for (int i = 0; i < 4; i++) acc[mt][nt][i] = 0.f;
            hacc[mt][nt][0] = 0u; hacc[mt][nt][1] = 0u;
        }

    uint32_t a_roff = (uint32_t)(m_base + (lane & 15)) * PITCH + ((lane >> 4) * 16);
    uint32_t b_roff = (uint32_t)(n_base + ((lane >> 4) * 8) + (lane & 7)) * PITCH + (((lane >> 3) & 1) * 16);

    g_load_stage3(sb, 0, 0, Ah, Al, Bh, Bl, row0, col0, tid);
    CP_COMMIT();

    for (int kc = 0; kc < 8; kc++) {
        if (kc + 1 < 8) g_load_stage3(sb, (kc+1) & 1, kc+1, Ah, Al, Bh, Bl, row0, col0, tid);
        CP_COMMIT();
        CP_WAIT1();
        __syncthreads();
        uint32_t st = sb + (kc & 1)*STAGE3_B;
        #pragma unroll
        for (int ks = 0; ks < 2; ks++) {
            uint32_t koff = ks * 32;
            uint32_t ah[2][4], al[2][4], bh[8][2], bl[8][2];
            #pragma unroll
            for (int mt = 0; mt < 2; mt++) {
                uint32_t ad = st + a_roff + (uint32_t)mt*16*PITCH + koff;
                ldsm_x4(ah[mt], ad);
                ldsm_x4(al[mt], ad + TILE_B);
            }
            #pragma unroll
            for (int p = 0; p < 4; p++) {
                uint32_t r4[4];
                uint32_t bd = st + 2*TILE_B + b_roff + (uint32_t)p*16*PITCH + koff;
                ldsm_x4(r4, bd);
                bh[2*p][0] = r4[0]; bh[2*p][1] = r4[1];
                bh[2*p+1][0] = r4[2]; bh[2*p+1][1] = r4[3];
                ldsm_x4(r4, bd + TILE_B);
                bl[2*p][0] = r4[0]; bl[2*p][1] = r4[1];
                bl[2*p+1][0] = r4[2]; bl[2*p+1][1] = r4[3];
            }
            #pragma unroll
            for (int mt = 0; mt < 2; mt++)
                #pragma unroll
                for (int nt = 0; nt < 8; nt++) {
                    mma16816(acc[mt][nt], ah[mt], bh[nt]);
                    mma16816h(hacc[mt][nt], ah[mt], bl[nt]);
                    mma16816h(hacc[mt][nt], al[mt], bh[nt]);
                }
        }
        __syncthreads();
    }

    int g = lane >> 2, t4 = lane & 3;
    #pragma unroll
    for (int mt = 0; mt < 2; mt++) {
        int r_lo = row0 + m_base + mt*16 + g;
        int r_hi = r_lo + 8;
        #pragma unroll
        for (int nt = 0; nt < 8; nt++) {
            int c = col0 + n_base + nt*8 + 2*t4;
            float2 h01 = __half22float2(*(__half2*)&hacc[mt][nt][0]);
            float2 h23 = __half22float2(*(__half2*)&hacc[mt][nt][1]);
            float cv0 = colv[c], cv1 = colv[c+1];
            *(float2*)(Out + (size_t)r_lo*out_ld + c) =
                make_float2(fmaf(alpha, acc[mt][nt][0] + h01.x, cv0),
                            fmaf(alpha, acc[mt][nt][1] + h01.y, cv1));
            *(float2*)(Out + (size_t)r_hi*out_ld + c) =
                make_float2(fmaf(alpha, acc[mt][nt][2] + h23.x, cv0),
                            fmaf(alpha, acc[mt][nt][3] + h23.y, cv1));
        }
    }
}

// single-pass dist GEMM (fp32 acc); stores s = embsq[c] - 2 x.e as fp16
__device__ __forceinline__ void g_load_stage1(
        uint32_t sb, int stage, int kc,
        const __half* Ah, const __half* Bh,
        int row0, int col0, int tid) {
    int k0 = kc*32;
    uint32_t sbase = sb + stage*STAGE1_B;
    #pragma unroll
    for (int j = 0; j < 4; j++) {
        int idx = j*256 + tid;
        int t = idx >> 9;
        int r = (idx >> 2) & 127;
        int s = idx & 3;
        const __half* gsrc = (t ? Bh + (size_t)(col0 + r)*CC : Ah + (size_t)(row0 + r)*CC) + k0 + s*8;
        uint32_t dst = sbase + t*TILE_B + r*PITCH + s*16;
        CP_ASYNC16(dst, gsrc);
    }
}

__global__ void __launch_bounds__(256)
gemm_dist(const __half* __restrict__ Ah, const __half* __restrict__ Bh,
          const float* __restrict__ colv,
          __half* __restrict__ OutH, int out_ld, float alpha) {
    extern __shared__ char smem[];
    uint32_t sb = smem_u32(smem);
    int tid = threadIdx.x, wid = tid >> 5, lane = tid & 31;
    int row0 = blockIdx.y * 128, col0 = blockIdx.x * 128;
    int m_base = (wid & 3) * 32;
    int n_base = (wid >> 2) * 64;

    float acc[2][8][4];
    #pragma unroll
    for (int mt = 0; mt < 2; mt++)
        #pragma unroll
        for (int nt = 0; nt < 8; nt++)
            #pragma unroll
            for (int i = 0; i < 4; i++) acc[mt][nt][i] = 0.f;

    uint32_t a_roff = (uint32_t)(m_base + (lane & 15)) * PITCH + ((lane >> 4) * 16);
    uint32_t b_roff = (uint32_t)(n_base + ((lane >> 4) * 8) + (lane & 7)) * PITCH + (((lane >> 3) & 1) * 16);

    g_load_stage1(sb, 0, 0, Ah, Bh, row0, col0, tid);
    CP_COMMIT();

    for (int kc = 0; kc < 8; kc++) {
        if (kc + 1 < 8) g_load_stage1(sb, (kc+1) & 1, kc+1, Ah, Bh, row0, col0, tid);
        CP_COMMIT();
        CP_WAIT1();
        __syncthreads();
        uint32_t st = sb + (kc & 1)*STAGE1_B;
        #pragma unroll
        for (int ks = 0; ks < 2; ks++) {
            uint32_t koff = ks * 32;
            uint32_t ah[2][4], bh[8][2];
            #pragma unroll
            for (int mt = 0; mt < 2; mt++)
                ldsm_x4(ah[mt], st + a_roff + (uint32_t)mt*16*PITCH + koff);
            #pragma unroll
            for (int p = 0; p < 4; p++) {
                uint32_t r4[4];
                ldsm_x4(r4, st + TILE_B + b_roff + (uint32_t)p*16*PITCH + koff);
                bh[2*p][0] = r4[0]; bh[2*p][1] = r4[1];
                bh[2*p+1][0] = r4[2]; bh[2*p+1][1] = r4[3];
            }
            #pragma unroll
            for (int mt = 0; mt < 2; mt++)
                #pragma unroll
                for (int nt = 0; nt < 8; nt++)
                    mma16816(acc[mt][nt], ah[mt], bh[nt]);
        }
        __syncthreads();
    }

    int g = lane >> 2, t4 = lane & 3;
    #pragma unroll
    for (int mt = 0; mt < 2; mt++) {
        int r_lo = row0 + m_base + mt*16 + g;
        int r_hi = r_lo + 8;
        #pragma unroll
        for (int nt = 0; nt < 8; nt++) {
            int c = col0 + n_base + nt*8 + 2*t4;
            float cv0 = colv[c], cv1 = colv[c+1];
            *(__half2*)(OutH + (size_t)r_lo*out_ld + c) =
                __floats2half2_rn(fmaf(alpha, acc[mt][nt][0], cv0), fmaf(alpha, acc[mt][nt][1], cv1));
            *(__half2*)(OutH + (size_t)r_hi*out_ld + c) =
                __floats2half2_rn(fmaf(alpha, acc[mt][nt][2], cv0), fmaf(alpha, acc[mt][nt][3], cv1));
        }
    }
}

// ================= attention (folded): scores = (Y+u).hn ; ztf = att.Z + diff =================
#define APAD 260
__global__ void __launch_bounds__(256) attn_kernel() {
    __shared__ float qs[16][APAD], ks[16][APAD];
    __shared__ float att[16][16];
    int x = blockIdx.x;
    int b = x >> 10;
    int s = x & (HWp - 1);
    int p0 = b*THW + s;                   // row for t=0
    const int pstr = HWp;                 // row stride per t
    int tid = threadIdx.x;
    const float inv_sxv = 1.0f/SXV;
    // phase 1: qs = Y (+u baked in GEMM bias), ks = hn reconstructed
    for (int e = tid; e < 16*256; e += 256) {
        int t = e >> 8, c = e & 255;
        size_t p = (size_t)(p0 + t*pstr);
        qs[t][c] = g_yz[p*512 + c];
        ks[t][c] = (__half2float(g_p1h[p*CC + c]) + __half2float(g_p1l[p*CC + c])) * inv_sxv;
    }
    __syncthreads();
    int i = tid >> 4, j = tid & 15;
    float acc = 0.f;
    #pragma unroll 8
    for (int c4 = 0; c4 < 64; c4++) {
        float4 a = *(const float4*)&qs[i][c4*4];
        float4 bb = *(const float4*)&ks[j][c4*4];
        acc = fmaf(a.x, bb.x, acc); acc = fmaf(a.y, bb.y, acc);
        acc = fmaf(a.z, bb.z, acc); acc = fmaf(a.w, bb.w, acc);
    }
    att[i][j] = acc * 0.0625f;
    __syncthreads();
    if (tid < 16) {
        float m = -3.4e38f;
        for (int jj = 0; jj < 16; jj++) m = fmaxf(m, att[tid][jj]);
        float ssum = 0.f;
        for (int jj = 0; jj < 16; jj++) { float e = expf(att[tid][jj]-m); att[tid][jj] = e; ssum += e; }
        float r = 1.0f/ssum;
        for (int jj = 0; jj < 16; jj++) att[tid][jj] *= r;
    }
    __syncthreads();
    // phase 2: qs = Z (cvec baked), ks = zp
    for (int e = tid; e < 16*256; e += 256) {
        int t = e >> 8, c = e & 255;
        size_t p = (size_t)(p0 + t*pstr);
        qs[t][c] = g_yz[p*512 + 256 + c];
        ks[t][c] = g_zp[p*CC + c];
    }
    __syncthreads();
    int c = tid;
    float vv[16];
    #pragma unroll
    for (int tk = 0; tk < 16; tk++) vv[tk] = qs[tk][c];
    #pragma unroll
    for (int tq = 0; tq < 16; tq++) {
        float o = 0.f;
        #pragma unroll
        for (int tk = 0; tk < 16; tk++) o = fmaf(att[tq][tk], vv[tk], o);
        float zc = ks[tq][c];
        float zm = tq ? ks[tq-1][c] : zc;
        float v = o + (zc - zm);                 // ztf
        size_t p = (size_t)(p0 + tq*pstr);
        g_q[p*CC + c] = v;
        g_p1h[p*CC + c] = __float2half_rn(v*SXV);
        float sq = v*v;
        #pragma unroll
        for (int off = 16; off; off >>= 1) sq += __shfl_xor_sync(0xffffffffu, sq, off);
        if ((tid & 31) == 0) atomicAdd(&g_xsq[NN + p0 + tq*pstr], sq);
    }
}

// warp-per-row reduce (unchanged)
__global__ void __launch_bounds__(256) vq_reduce_kernel(int branch, const __half* __restrict__ DIST,
                                                        const float* __restrict__ X,
                                                        const float* __restrict__ EMB) {
    __shared__ float swarp[8][1024];
    int tid = threadIdx.x, w = tid >> 5, lane = tid & 31;
    int row0 = blockIdx.x * 64;
    float accx[16], accy[16];
    #pragma unroll
    for (int j = 0; j < 16; j++) { accx[j] = 0.f; accy[j] = 0.f; }
    for (int rr = 0; rr < 8; rr++) {
        int row = row0 + w*8 + rr;
        const __half2* dr = (const __half2*)(DIST + (size_t)row*KCB);
        float sA = g_xsq[branch*NN + row];
        float ivx[16], ivy[16];
        float lsum = 0.f, m1v = 0.f, m2v = 0.f; int i1 = 0;
        #pragma unroll
        for (int j = 0; j < 16; j++) {
            float2 s2 = __half22float2(dr[j*32 + lane]);
            float ix = rcp_approx(sA + s2.x);
            float iy = rcp_approx(sA + s2.y);
            ivx[j] = ix; ivy[j] = iy; lsum += ix + iy;
            int cb = 2*(j*32 + lane);
            if (ix > m1v) { m2v = m1v; m1v = ix; i1 = cb; } else m2v = fmaxf(m2v, ix);
            if (iy > m1v) { m2v = m1v; m1v = iy; i1 = cb+1; } else m2v = fmaxf(m2v, iy);
        }
        #pragma unroll
        for (int o = 16; o; o >>= 1) {
            lsum += __shfl_xor_sync(0xffffffffu, lsum, o);
            float o1 = __shfl_xor_sync(0xffffffffu, m1v, o);
            int   oi = __shfl_xor_sync(0xffffffffu, i1, o);
            float o2 = __shfl_xor_sync(0xffffffffu, m2v, o);
            if (o1 > m1v || (o1 == m1v && oi < i1)) { m2v = fmaxf(m1v, o2); m1v = o1; i1 = oi; }
            else m2v = fmaxf(m2v, o1);
        }
        int idxf = i1;
        float d1 = rcp_approx(m1v);
        float d2 = rcp_approx(m2v);
        if (d2 - d1 <= REFINE_TH) {
            float xr[8];
            #pragma unroll
            for (int k = 0; k < 8; k++) xr[k] = X[(size_t)row*CC + lane + 32*k];
            float thr_iv = rcp_approx(d1 + REFINE_TH) * (1.0f - 2e-6f);
            float bestd = 3.4e38f; int besti = 0x7fffffff;
            for (int j = 0; j < 16; j++) {
                #pragma unroll
                for (int pass = 0; pass < 2; pass++) {
                    float iv = pass ? ivy[j] : ivx[j];
                    unsigned bal = __ballot_sync(0xffffffffu, iv >= thr_iv);
                    while (bal) {
                        int src = __ffs(bal) - 1; bal &= bal - 1;
                        int cidx = 2*(j*32 + src) + pass;
                        const float* er = EMB + (size_t)cidx*CC;
                        float dot = 0.f;
                        #pragma unroll
                        for (int k = 0; k < 8; k++) dot = fmaf(xr[k], er[lane + 32*k], dot);
                        #pragma unroll
                        for (int o = 16; o; o >>= 1) dot += __shfl_xor_sync(0xffffffffu, dot, o);
                        float de = fmaf(-2.f, dot, sA + g_embsq[branch*KCB + cidx]);
                        if (de < bestd || (de == bestd && cidx < besti)) { bestd = de; besti = cidx; }
                    }
                }
            }
            idxf = besti;
        }
        if (lane == 0) {
            g_idx[branch*NN + row] = idxf;
            atomicAdd(&g_hist[branch*KCB + idxf], 1);
        }
        float irs = 1.0f/lsum;
        #pragma unroll
        for (int j = 0; j < 16; j++) { accx[j] += ivx[j]*irs; accy[j] += ivy[j]*irs; }
    }
    #pragma unroll
    for (int j = 0; j < 16; j++) {
        swarp[w][j*64 + 2*lane]     = accx[j];
        swarp[w][j*64 + 2*lane + 1] = accy[j];
    }
    __syncthreads();
    for (int c = tid; c < 1024; c += 256) {
        float s = 0.f;
        #pragma unroll
        for (int ww = 0; ww < 8; ww++) s += swarp[ww][c];
        atomicAdd(&g_avg[branch*KCB + c], s);
    }
}

__global__ void assemble_kernel(const float* __restrict__ emb_s,
                                const float* __restrict__ emb_t,
                                float* __restrict__ out) {
    __shared__ float tl[32][33];
    __shared__ float mred[256];
    int b = blockIdx.z, c0 = blockIdx.y*32, s0 = blockIdx.x*32;
    int tx = threadIdx.x, ty = threadIdx.y;
    float lm = 0.f;
    #pragma unroll
    for (int i = 0; i < 4; i++) {
        int th = s0 + ty + i*8;
        int p = b*THW + th;
        int is = g_idx[p], it = g_idx[NN + p];
        int c = c0 + tx;
        float zpv = g_zp[(size_t)p*CC + c];
        float zq  = emb_t[(size_t)it*CC + c] + emb_s[(size_t)is*CC + c];
        float d = zq - zpv;
        lm += d*d;
        tl[ty + i*8][tx] = zpv + d;
    }
    int tid = ty*32 + tx;
    mred[tid] = lm;
    __syncthreads();
    for (int s = 128; s; s >>= 1) { if (tid < s) mred[tid] += mred[tid+s]; __syncthreads(); }
    if (tid == 0) atomicAdd(&g_mse, (double)mred[0]);
    #pragma unroll
    for (int i = 0; i < 4; i++) {
        int c  = c0 + ty + i*8;
        int th = s0 + tx;
        out[((size_t)(b*CC + c))*THW + th] = tl[tx][ty + i*8];
    }
}

__global__ void ind_write_kernel(float* __restrict__ out) {
    int gid = blockIdx.x*256 + threadIdx.x;
    int br = gid >> 16;
    int o  = gid & (NN - 1);
    int b = o / (TT*HWp);
    int rem = o - b*(TT*HWp);
    int t = rem / HWp;
    int s = rem & (HWp - 1);
    int src = (t*BB + b)*HWp + s;
    out[(br ? OFF_INDT : OFF_INDS) + o] = (float)g_idx[br*NN + src];
}

__global__ void __launch_bounds__(1024) finalize_kernel(float* __restrict__ out) {
    __shared__ double sd[1024];
    int t = threadIdx.x;
    if (t == 0) out[OFF_LOSS] = (float)(1.25 * g_mse / ((double)NN * (double)CC));
    for (int br = 0; br < 2; br++) {
        double e = (double)g_hist[br*KCB + t] / (double)NN;
        sd[t] = e * log(e + 1e-10);
        __syncthreads();
        for (int s = 512; s; s >>= 1) { if (t < s) sd[t] += sd[t+s]; __syncthreads(); }
        if (t == 0) out[br == 0 ? OFF_PERPS : OFF_PERPT] = (float)exp(-sd[0]);
        __syncthreads();
    }
    double kl[2];
    for (int br = 0; br < 2; br++) {
        double a = (double)g_avg[br*KCB + t] / (double)NN;
        sd[t] = a; __syncthreads();
        for (int s = 512; s; s >>= 1) { if (t < s) sd[t] = fmax(sd[t], sd[t+s]); __syncthreads(); }
        double m = sd[0]; __syncthreads();
        sd[t] = exp(a - m); __syncthreads();
        for (int s = 512; s; s >>= 1) { if (t < s) sd[t] += sd[t+s]; __syncthreads(); }
        double Z = sd[0]; __syncthreads();
        sd[t] = a; __syncthreads();
        for (int s = 512; s; s >>= 1) { if (t < s) sd[t] += sd[t+s]; __syncthreads(); }
        double SA = sd[0]; __syncthreads();
        double lse = m + log(Z);
        double tgt = 1.0 / (double)KCB;
        kl[br] = tgt * (log(tgt) + lse - SA / (double)KCB);
    }
    if (t == 0) out[OFF_LOSS2] = (float)(0.1 * (kl[0] + kl[1]));
}

// ================= host =================

extern "C" void kernel_launch(void* const* d_in, const int* in_sizes, int n_in,
                              void* d_out, int out_size) {
    (void)in_sizes; (void)n_in; (void)out_size;
    const float* z     = (const float*)d_in[0];
    const float* emb_s = (const float*)d_in[1];
    const float* emb_t = (const float*)d_in[2];
    const float* gamma = (const float*)d_in[3];
    const float* beta  = (const float*)d_in[4];
    const float* wq = (const float*)d_in[5];
    const float* bq = (const float*)d_in[6];
    const float* wk = (const float*)d_in[7];
    const float* bv = (const float*)d_in[10];
    const float* wv = (const float*)d_in[9];
    const float* wp = (const float*)d_in[11];
    const float* bp = (const float*)d_in[12];
    float* out = (float*)d_out;
    (void)d_in[8];

    float *p_zp, *p_q, *p_yz, *p_embsq, *p_bias;
    __half *p1h, *p1l, *p2h, *pwh, *pwl, *pebh, *pds, *pdt;
    cudaGetSymbolAddress((void**)&p_zp, g_zp);
    cudaGetSymbolAddress((void**)&p_q,  g_q);
    cudaGetSymbolAddress((void**)&p_yz, g_yz);
    cudaGetSymbolAddress((void**)&pds, g_dist_s);
    cudaGetSymbolAddress((void**)&pdt, g_dist_t);
    cudaGetSymbolAddress((void**)&p_embsq, g_embsq);
    cudaGetSymbolAddress((void**)&p_bias, g_bias);
    cudaGetSymbolAddress((void**)&p1h, g_p1h);
    cudaGetSymbolAddress((void**)&p1l, g_p1l);
    cudaGetSymbolAddress((void**)&p2h, g_p2h);
    cudaGetSymbolAddress((void**)&pwh, g_wh);
    cudaGetSymbolAddress((void**)&pwl, g_wl);
    cudaGetSymbolAddress((void**)&pebh, g_ebh);

    static cudaStream_t s2 = nullptr;
    static cudaEvent_t evA, evB, evC, evD;
    if (!s2) {
        cudaStreamCreateWithFlags(&s2, cudaStreamNonBlocking);
        cudaEventCreateWithFlags(&evA, cudaEventDisableTiming);
        cudaEventCreateWithFlags(&evB, cudaEventDisableTiming);
        cudaEventCreateWithFlags(&evC, cudaEventDisableTiming);
        cudaEventCreateWithFlags(&evD, cudaEventDisableTiming);
        cudaFuncSetAttribute(gemm3fp16, cudaFuncAttributeMaxDynamicSharedMemorySize, GSM3);
        cudaFuncSetAttribute(gemm_dist, cudaFuncAttributeMaxDynamicSharedMemorySize, GSM1);
    }

    zero_kernel<<<512, 256>>>();
    cudaEventRecord(evA, 0);
    cudaStreamWaitEvent(s2, evA, 0);
    embsplit_kernel<<<2*KCB, 256, 0, s2>>>(emb_s, emb_t);
    wprod_kernel<<<512, 256, 0, s2>>>(wq, wk, wv, wp, bq, bv, bp);
    cudaEventRecord(evB, s2);

    gn_partial<<<2048, 256>>>(z);
    transpose_norm_kernel<<<dim3(THW/32, CC/32, BB), dim3(32, 8)>>>(z, gamma, beta);
    cudaEventRecord(evC, 0);

    // spatial VQ branch on s2
    cudaStreamWaitEvent(s2, evC, 0);
    gemm_dist<<<dim3(KCB/128, NN/128), 256, GSM1, s2>>>(p2h, pebh, p_embsq, pds, KCB, ALPHA_DIST);
    vq_reduce_kernel<<<NN/64, 256, 0, s2>>>(0, pds, p_zp, emb_s);
    cudaEventRecord(evD, s2);

    // temporal chain: Y|Z GEMM -> attn -> dist_t -> vq_t
    cudaStreamWaitEvent(0, evB, 0);
    gemm3fp16<<<dim3(2*CC/128, NN/128), 256, GSM3>>>(p1h, p1l, pwh, pwl, p_bias, p_yz, 2*CC, ALPHA_CONV);
    attn_kernel<<<BB*HWp, 256>>>();
    gemm_dist<<<dim3(KCB/128, NN/128), 256, GSM1>>>(p1h, pebh + (size_t)KCB*CC, p_embsq + KCB,
                                                    pdt, KCB, ALPHA_DIST);
    vq_reduce_kernel<<<NN/64, 256>>>(1, pdt, p_q, emb_t);

    cudaStreamWaitEvent(0, evD, 0);
    assemble_kernel<<<dim3(THW/32, CC/32, BB), dim3(32, 8)>>>(emb_s, emb_t, out);
    ind_write_kernel<<<2*NN/256, 256>>>(out);
    finalize_kernel<<<1, 1024>>>(out);
}